// round 1
// baseline (speedup 1.0000x reference)
#include <cuda_runtime.h>
#include <math.h>

#define BATCH 8
#define SEQ 1024
#define DIM 768
#define NHEAD 12
#define HD 64
#define QKVC 2304
#define HIDDEN 3072
#define EPSI 1e-5f

// ---------------- scratch (device globals: allocation-free contract) --------
__device__ float g_xn [2ull*BATCH*SEQ*DIM];     // normalized inputs (both streams)
__device__ float g_qkv[2ull*BATCH*SEQ*QKVC];    // qkv after head-LN, layout (dir,B,N,3,H,64)
__device__ float g_S  [(size_t)BATCH*NHEAD*SEQ*SEQ]; // attention scores scratch (one dir at a time)
__device__ float g_ctx[2ull*BATCH*SEQ*DIM];     // attention output (dir = q-dir), (B,N,H*64)
__device__ float g_p  [2ull*BATCH*SEQ*DIM];     // proj output
__device__ float g_res[2ull*BATCH*SEQ*DIM];     // post-attention residual
__device__ float g_ln2[2ull*BATCH*SEQ*DIM];
__device__ float g_h  [2ull*BATCH*SEQ*HIDDEN];  // fc1 output

// ---------------- LayerNorm over DIM=768, one block per row ----------------
__global__ void ln_kernel(const float* __restrict__ x, const float* __restrict__ w,
                          const float* __restrict__ b, float* __restrict__ out) {
    int row = blockIdx.x;
    const float* xr = x + (size_t)row * DIM;
    float* orow = out + (size_t)row * DIM;
    float v[3];
    float s = 0.f, ss = 0.f;
#pragma unroll
    for (int i = 0; i < 3; i++) {
        v[i] = xr[threadIdx.x + i * 256];
        s += v[i]; ss += v[i] * v[i];
    }
    __shared__ float red0[8], red1[8];
    int lane = threadIdx.x & 31, wp = threadIdx.x >> 5;
#pragma unroll
    for (int o = 16; o; o >>= 1) {
        s  += __shfl_xor_sync(0xffffffffu, s, o);
        ss += __shfl_xor_sync(0xffffffffu, ss, o);
    }
    if (lane == 0) { red0[wp] = s; red1[wp] = ss; }
    __syncthreads();
    s = 0.f; ss = 0.f;
#pragma unroll
    for (int i = 0; i < 8; i++) { s += red0[i]; ss += red1[i]; }
    float mean = s * (1.f / DIM);
    float var  = ss * (1.f / DIM) - mean * mean;
    float inv  = rsqrtf(var + EPSI);
#pragma unroll
    for (int i = 0; i < 3; i++) {
        int c = threadIdx.x + i * 256;
        orow[c] = (v[i] - mean) * inv * w[c] + b[c];
    }
}

// ---------------- per-head LN: one warp per 64-elem chunk (in-place) -------
__global__ void head_ln_kernel(float* __restrict__ qkv, const float* __restrict__ w,
                               const float* __restrict__ b, size_t nchunks) {
    size_t warp = ((size_t)blockIdx.x * blockDim.x + threadIdx.x) >> 5;
    int lane = threadIdx.x & 31;
    if (warp >= nchunks) return;
    float* ptr = qkv + warp * 64;
    float x0 = ptr[lane], x1 = ptr[lane + 32];
    float s = x0 + x1, ss = x0 * x0 + x1 * x1;
#pragma unroll
    for (int o = 16; o; o >>= 1) {
        s  += __shfl_xor_sync(0xffffffffu, s, o);
        ss += __shfl_xor_sync(0xffffffffu, ss, o);
    }
    float mean = s * (1.f / 64.f);
    float var  = ss * (1.f / 64.f) - mean * mean;
    float inv  = rsqrtf(var + EPSI);
    ptr[lane]      = (x0 - mean) * inv * w[lane]      + b[lane];
    ptr[lane + 32] = (x1 - mean) * inv * w[lane + 32] + b[lane + 32];
}

// ---------------- generic fp32 GEMM: C = act(A @ W^T + bias) [+ resid] -----
// A: (M,K) row-major, W: (N,K) row-major. act: 0=none, 1=exact gelu.
#define BM 128
#define BN 128
#define BK 8
#define TM 8
#define TN 8
__global__ __launch_bounds__(256) void gemm_kernel(
    const float* __restrict__ A, const float* __restrict__ W,
    const float* __restrict__ bias, const float* __restrict__ resid,
    float* __restrict__ C, int M, int N, int K, int act)
{
    __shared__ float As[BK][BM + 4];
    __shared__ float Bs[BK][BN + 4];
    int tid = threadIdx.x;
    int tr = tid >> 4, tc = tid & 15;
    int rowBase = blockIdx.y * BM, colBase = blockIdx.x * BN;
    float acc[TM][TN];
#pragma unroll
    for (int i = 0; i < TM; i++)
#pragma unroll
        for (int j = 0; j < TN; j++) acc[i][j] = 0.f;

    for (int k0 = 0; k0 < K; k0 += BK) {
#pragma unroll
        for (int i = 0; i < 4; i++) {              // A tile: 128x8
            int l = tid + i * 256;
            int r = l >> 3, c = l & 7;
            As[c][r] = A[(size_t)(rowBase + r) * K + k0 + c];
        }
#pragma unroll
        for (int i = 0; i < 4; i++) {              // W tile: 128 rows of W, 8 k
            int l = tid + i * 256;
            int c = l >> 3, r = l & 7;             // c = n within tile, r = k
            Bs[r][c] = W[(size_t)(colBase + c) * K + k0 + r];
        }
        __syncthreads();
#pragma unroll
        for (int k = 0; k < BK; k++) {
            float ra[TM], rb[TN];
#pragma unroll
            for (int i = 0; i < TM; i++) ra[i] = As[k][tr * TM + i];
#pragma unroll
            for (int j = 0; j < TN; j++) rb[j] = Bs[k][tc * TN + j];
#pragma unroll
            for (int i = 0; i < TM; i++)
#pragma unroll
                for (int j = 0; j < TN; j++) acc[i][j] += ra[i] * rb[j];
        }
        __syncthreads();
    }

#pragma unroll
    for (int i = 0; i < TM; i++) {
        int gr = rowBase + tr * TM + i;
        size_t rb_off = (size_t)gr * N;
#pragma unroll
        for (int j = 0; j < TN; j++) {
            int gc = colBase + tc * TN + j;
            float v = acc[i][j];
            if (bias) v += bias[gc];
            if (act == 1) v = 0.5f * v * (1.f + erff(v * 0.70710678118654752f));
            if (resid) v += resid[rb_off + gc];
            C[rb_off + gc] = v;
        }
    }
}

// ---------------- attention scores: S = scale * Q @ K^T (64x64 tiles) ------
__global__ __launch_bounds__(256) void attn_scores_kernel(
    const float* __restrict__ qkv, int dirQ, float* __restrict__ S)
{
    int bh = blockIdx.z;
    int b = bh / NHEAD, h = bh % NHEAD;
    const float* qbase = qkv + ((size_t)(dirQ * BATCH + b)) * SEQ * QKVC + h * HD;
    const float* kbase = qkv + ((size_t)((1 - dirQ) * BATCH + b)) * SEQ * QKVC + DIM + h * HD;
    __shared__ float Qs[64][65];   // transposed: Qs[k][i]
    __shared__ float Ks[64][65];   // transposed: Ks[k][j]
    int i0 = blockIdx.y * 64, j0 = blockIdx.x * 64;
    int tid = threadIdx.x;
#pragma unroll
    for (int t = 0; t < 16; t++) {
        int l = tid + t * 256;
        int n = l >> 6, k = l & 63;
        Qs[k][n] = qbase[(size_t)(i0 + n) * QKVC + k];
        Ks[k][n] = kbase[(size_t)(j0 + n) * QKVC + k];
    }
    __syncthreads();
    int tr = tid >> 4, tc = tid & 15;
    float acc[4][4] = {};
#pragma unroll
    for (int k = 0; k < 64; k++) {
        float ra[4], rb[4];
#pragma unroll
        for (int i = 0; i < 4; i++) ra[i] = Qs[k][tr * 4 + i];
#pragma unroll
        for (int j = 0; j < 4; j++) rb[j] = Ks[k][tc * 4 + j];
#pragma unroll
        for (int i = 0; i < 4; i++)
#pragma unroll
            for (int j = 0; j < 4; j++) acc[i][j] += ra[i] * rb[j];
    }
    const float scale = 0.125f;   // hd^-0.5
#pragma unroll
    for (int i = 0; i < 4; i++) {
        size_t off = ((size_t)bh * SEQ + i0 + tr * 4 + i) * SEQ + j0 + tc * 4;
        float4 v = make_float4(acc[i][0] * scale, acc[i][1] * scale,
                               acc[i][2] * scale, acc[i][3] * scale);
        *(float4*)&S[off] = v;
    }
}

// ---------------- row softmax over 1024, one block per row -----------------
__global__ void softmax_kernel(float* __restrict__ S) {
    size_t row = blockIdx.x;
    float* r = S + row * SEQ;
    float v[4];
    float mx = -1e30f;
#pragma unroll
    for (int i = 0; i < 4; i++) { v[i] = r[threadIdx.x + i * 256]; mx = fmaxf(mx, v[i]); }
    __shared__ float red[8];
    int lane = threadIdx.x & 31, wp = threadIdx.x >> 5;
#pragma unroll
    for (int o = 16; o; o >>= 1) mx = fmaxf(mx, __shfl_xor_sync(0xffffffffu, mx, o));
    if (lane == 0) red[wp] = mx;
    __syncthreads();
    mx = red[0];
#pragma unroll
    for (int i = 1; i < 8; i++) mx = fmaxf(mx, red[i]);
    float s = 0.f;
#pragma unroll
    for (int i = 0; i < 4; i++) { v[i] = __expf(v[i] - mx); s += v[i]; }
#pragma unroll
    for (int o = 16; o; o >>= 1) s += __shfl_xor_sync(0xffffffffu, s, o);
    __syncthreads();                       // protect red[] reuse
    if (lane == 0) red[wp] = s;
    __syncthreads();
    s = 0.f;
#pragma unroll
    for (int i = 0; i < 8; i++) s += red[i];
    float inv = 1.f / s;
#pragma unroll
    for (int i = 0; i < 4; i++) r[threadIdx.x + i * 256] = v[i] * inv;
}

// ---------------- AV: ctx = P @ V, 64 query rows per block -----------------
__global__ __launch_bounds__(256) void attn_av_kernel(
    const float* __restrict__ S, const float* __restrict__ qkv, int dirQ,
    float* __restrict__ ctx)
{
    int bh = blockIdx.y;
    int b = bh / NHEAD, h = bh % NHEAD;
    const float* P = S + (size_t)bh * SEQ * SEQ;
    const float* vbase = qkv + ((size_t)((1 - dirQ) * BATCH + b)) * SEQ * QKVC + 2 * DIM + h * HD;
    __shared__ float Ps[64][65];  // transposed: Ps[k][i]
    __shared__ float Vs[64][64];  // Vs[k][d]
    int i0 = blockIdx.x * 64;
    int tid = threadIdx.x;
    int tr = tid >> 4, tc = tid & 15;
    float acc[4][4] = {};
    for (int k0 = 0; k0 < SEQ; k0 += 64) {
#pragma unroll
        for (int t = 0; t < 16; t++) {
            int l = tid + t * 256;
            int n = l >> 6, k = l & 63;
            Ps[k][n] = P[(size_t)(i0 + n) * SEQ + k0 + k];
            Vs[n][k] = vbase[(size_t)(k0 + n) * QKVC + k];
        }
        __syncthreads();
#pragma unroll
        for (int k = 0; k < 64; k++) {
            float ra[4], rb[4];
#pragma unroll
            for (int i = 0; i < 4; i++) ra[i] = Ps[k][tr * 4 + i];
#pragma unroll
            for (int j = 0; j < 4; j++) rb[j] = Vs[k][tc * 4 + j];
#pragma unroll
            for (int i = 0; i < 4; i++)
#pragma unroll
                for (int j = 0; j < 4; j++) acc[i][j] += ra[i] * rb[j];
        }
        __syncthreads();
    }
    float* out = ctx + ((size_t)(dirQ * BATCH + b) * SEQ + i0) * DIM + h * HD;
#pragma unroll
    for (int i = 0; i < 4; i++) {
        float4 v = make_float4(acc[i][0], acc[i][1], acc[i][2], acc[i][3]);
        *(float4*)&out[(size_t)(tr * 4 + i) * DIM + tc * 4] = v;
    }
}

// ------- residual: res[dir] = xn[dir] + p[other] + remap(q[other]) ---------
// remap implements the faithful q.reshape(B,N,H*D) without head transpose.
__global__ void residual_kernel(const float* __restrict__ xn, const float* __restrict__ p,
                                const float* __restrict__ qkv, float* __restrict__ res)
{
    const size_t BNC = (size_t)BATCH * SEQ * DIM;
    size_t idx = (size_t)blockIdx.x * 256 + threadIdx.x;
    if (idx >= 2 * BNC) return;
    int dir = (int)(idx / BNC);
    size_t rem = idx - (size_t)dir * BNC;
    int b = (int)(rem / (SEQ * DIM));
    int t = (int)(rem % (SEQ * DIM));          // t = n*768 + c
    int other = 1 - dir;
    int h  = t >> 16;                           // t / (N*HD) = t / 65536
    int r2 = t & 65535;
    int n2 = r2 >> 6;
    int d  = r2 & 63;
    float qv = qkv[((size_t)(other * BATCH + b) * SEQ + n2) * QKVC + h * HD + d];
    res[idx] = xn[idx] + p[(size_t)other * BNC + rem] + qv;
}

// ---------------------------------------------------------------------------
extern "C" void kernel_launch(void* const* d_in, const int* in_sizes, int n_in,
                              void* d_out, int out_size) {
    const float* before  = (const float*)d_in[0];
    const float* after   = (const float*)d_in[1];
    const float* norm1_w = (const float*)d_in[2];
    const float* norm1_b = (const float*)d_in[3];
    const float* qkv_w   = (const float*)d_in[4];
    const float* hln_w   = (const float*)d_in[5];
    const float* hln_b   = (const float*)d_in[6];
    const float* proj_w  = (const float*)d_in[7];
    const float* proj_b  = (const float*)d_in[8];
    const float* norm2_w = (const float*)d_in[9];
    const float* norm2_b = (const float*)d_in[10];
    const float* fc1_w   = (const float*)d_in[11];
    const float* fc1_b   = (const float*)d_in[12];
    const float* fc2_w   = (const float*)d_in[13];
    const float* fc2_b   = (const float*)d_in[14];
    float* out = (float*)d_out;

    float *xn, *qkv, *S, *ctx, *p, *res, *ln2, *hbuf;
    cudaGetSymbolAddress((void**)&xn,  g_xn);
    cudaGetSymbolAddress((void**)&qkv, g_qkv);
    cudaGetSymbolAddress((void**)&S,   g_S);
    cudaGetSymbolAddress((void**)&ctx, g_ctx);
    cudaGetSymbolAddress((void**)&p,   g_p);
    cudaGetSymbolAddress((void**)&res, g_res);
    cudaGetSymbolAddress((void**)&ln2, g_ln2);
    cudaGetSymbolAddress((void**)&hbuf, g_h);

    const size_t BNC = (size_t)BATCH * SEQ * DIM;
    const int ROWS1 = BATCH * SEQ;          // 8192
    const int ROWS2 = 2 * ROWS1;            // 16384

    // 1. norm1 on both streams
    ln_kernel<<<ROWS1, 256>>>(before, norm1_w, norm1_b, xn);
    ln_kernel<<<ROWS1, 256>>>(after,  norm1_w, norm1_b, xn + BNC);

    // 2. fused-stream QKV GEMM (no bias)
    gemm_kernel<<<dim3(QKVC / BN, ROWS2 / BM), 256>>>(
        xn, qkv_w, nullptr, nullptr, qkv, ROWS2, QKVC, DIM, 0);

    // 3. per-head LN (in place)
    {
        size_t nchunks = (size_t)ROWS2 * QKVC / 64;   // 589824
        int blocks = (int)((nchunks * 32 + 255) / 256);
        head_ln_kernel<<<blocks, 256>>>(qkv, hln_w, hln_b, nchunks);
    }

    // 4. cross attention, both directions (S buffer reused serially)
    for (int dir = 0; dir < 2; dir++) {
        attn_scores_kernel<<<dim3(SEQ / 64, SEQ / 64, BATCH * NHEAD), 256>>>(qkv, dir, S);
        softmax_kernel<<<BATCH * NHEAD * SEQ, 256>>>(S);
        attn_av_kernel<<<dim3(SEQ / 64, BATCH * NHEAD), 256>>>(S, qkv, dir, ctx);
    }

    // 5. output projection (both streams)
    gemm_kernel<<<dim3(DIM / BN, ROWS2 / BM), 256>>>(
        ctx, proj_w, proj_b, nullptr, p, ROWS2, DIM, DIM, 0);

    // 6. attention residual with cross-stream swap + faithful q-remap
    residual_kernel<<<(int)((2 * BNC + 255) / 256), 256>>>(xn, p, qkv, res);

    // 7. norm2
    ln_kernel<<<ROWS2, 256>>>(res, norm2_w, norm2_b, ln2);

    // 8. MLP: fc1 + exact GELU fused
    gemm_kernel<<<dim3(HIDDEN / BN, ROWS2 / BM), 256>>>(
        ln2, fc1_w, fc1_b, nullptr, hbuf, ROWS2, HIDDEN, DIM, 1);

    // 9. fc2 + bias + residual, straight into d_out (before_o then after_o)
    gemm_kernel<<<dim3(DIM / BN, ROWS2 / BM), 256>>>(
        hbuf, fc2_w, fc2_b, res, out, ROWS2, DIM, HIDDEN, 0);
}

// round 2
// speedup vs baseline: 2.9742x; 2.9742x over previous
#include <cuda_runtime.h>
#include <math.h>
#include <stdint.h>

#define BATCH 8
#define SEQ 1024
#define DIM 768
#define NHEAD 12
#define HD 64
#define QKVC 2304
#define HIDDEN 3072
#define EPSI 1e-5f

// ---------------- scratch (device globals: allocation-free contract) --------
__device__ float g_xn [2ull*BATCH*SEQ*DIM];
__device__ float g_qkv[2ull*BATCH*SEQ*QKVC];
__device__ float g_S  [(size_t)BATCH*NHEAD*SEQ*SEQ];
__device__ float g_ctx[2ull*BATCH*SEQ*DIM];
__device__ float g_p  [2ull*BATCH*SEQ*DIM];
__device__ float g_res[2ull*BATCH*SEQ*DIM];
__device__ float g_ln2[2ull*BATCH*SEQ*DIM];
__device__ float g_h  [2ull*BATCH*SEQ*HIDDEN];

// ---------------- async copy helpers ---------------------------------------
__device__ __forceinline__ void cp_async16(uint32_t smem, const void* g) {
    asm volatile("cp.async.cg.shared.global [%0], [%1], 16;" :: "r"(smem), "l"(g));
}
__device__ __forceinline__ void cp_commit() {
    asm volatile("cp.async.commit_group;");
}
template<int N> __device__ __forceinline__ void cp_wait() {
    asm volatile("cp.async.wait_group %0;" :: "n"(N));
}

// ---------------- m16n8k8 tf32 mma -----------------------------------------
__device__ __forceinline__ void mma_tf32(float* c, const uint32_t* a, const uint32_t* b) {
    asm volatile(
        "mma.sync.aligned.m16n8k8.row.col.f32.tf32.tf32.f32 "
        "{%0,%1,%2,%3}, {%4,%5,%6,%7}, {%8,%9}, {%0,%1,%2,%3};"
        : "+f"(c[0]), "+f"(c[1]), "+f"(c[2]), "+f"(c[3])
        : "r"(a[0]), "r"(a[1]), "r"(a[2]), "r"(a[3]), "r"(b[0]), "r"(b[1]));
}

// ---------------- universal batched tf32 tensor-core GEMM -------------------
// C = act(alpha * A @ op(B) + bias) [+ resid]
// A: (M,K) row-major, lda. TRANSB=0: B is (N,K) row-major (i.e. W, C=A@W^T).
// TRANSB=1: B is (K,N) row-major (C=A@B). Batch z: off = (z/nh)*strb + (z%nh)*strh.
// ACT: 0 none, 1 exact GELU.
template<int BM, int BN, int BK, int WM, int WN, int TRANSB, int ACT>
__global__ void __launch_bounds__((BM/WM)*(BN/WN)*32)
mma_gemm(const float* __restrict__ A, int lda, long long strAb, long long strAh,
         const float* __restrict__ B, int ldb, long long strBb, long long strBh,
         const float* __restrict__ bias, const float* __restrict__ resid,
         float* __restrict__ C, int ldc, long long strCb, long long strCh,
         int K, int nh, float alpha)
{
    constexpr int NW  = (BM/WM)*(BN/WN);
    constexpr int NT  = NW * 32;
    constexpr int SA  = BK + 4;                 // A m-major smem stride (floats)
    constexpr int BRW = TRANSB ? BK : BN;       // B smem rows
    constexpr int SB  = TRANSB ? (BN + 8) : (BK + 4);
    constexpr int MI  = WM / 16;
    constexpr int NI  = WN / 8;

    __shared__ float As[2][BM][SA];
    __shared__ float Bs[2][BRW][SB];

    const int tid  = threadIdx.x;
    const int lane = tid & 31;
    const int wid  = tid >> 5;
    const int g    = lane >> 2;    // group id 0..7
    const int t    = lane & 3;     // thread-in-group 0..3

    constexpr int WROWS = BM / WM;
    const int wr = wid % WROWS, wc = wid / WROWS;
    const int mB = wr * WM, nB = wc * WN;

    const int z = blockIdx.z;
    const int zb = z / nh, zh = z - zb * nh;
    const float* Ab = A + (size_t)zb * strAb + (size_t)zh * strAh;
    const float* Bb = B + (size_t)zb * strBb + (size_t)zh * strBh;
    float*       Cb = C + (size_t)zb * strCb + (size_t)zh * strCh;

    const int m0 = blockIdx.y * BM;
    const int n0 = blockIdx.x * BN;

    auto load_tile = [&](int buf, int k0) {
        // A: BM x BK, m-major in smem
        {
            const float* src = Ab + (size_t)m0 * lda + k0;
            constexpr int TOT = BM * BK / 4;
#pragma unroll
            for (int l = tid; l < TOT; l += NT) {
                int row = l / (BK / 4), q = l % (BK / 4);
                uint32_t dst = (uint32_t)__cvta_generic_to_shared(&As[buf][row][q * 4]);
                cp_async16(dst, src + (size_t)row * lda + q * 4);
            }
        }
        if (!TRANSB) {
            // B(N,K): rows of W, n-major in smem
            const float* src = Bb + (size_t)n0 * ldb + k0;
            constexpr int TOT = BN * BK / 4;
#pragma unroll
            for (int l = tid; l < TOT; l += NT) {
                int row = l / (BK / 4), q = l % (BK / 4);
                uint32_t dst = (uint32_t)__cvta_generic_to_shared(&Bs[buf][row][q * 4]);
                cp_async16(dst, src + (size_t)row * ldb + q * 4);
            }
        } else {
            // B(K,N): rows of B, k-major in smem
            const float* src = Bb + (size_t)k0 * ldb + n0;
            constexpr int TOT = BK * BN / 4;
#pragma unroll
            for (int l = tid; l < TOT; l += NT) {
                int row = l / (BN / 4), q = l % (BN / 4);
                uint32_t dst = (uint32_t)__cvta_generic_to_shared(&Bs[buf][row][q * 4]);
                cp_async16(dst, src + (size_t)row * ldb + q * 4);
            }
        }
        cp_commit();
    };

    float acc[MI][NI][4];
#pragma unroll
    for (int mi = 0; mi < MI; mi++)
#pragma unroll
        for (int ni = 0; ni < NI; ni++)
#pragma unroll
            for (int r = 0; r < 4; r++) acc[mi][ni][r] = 0.f;

    const int nIter = K / BK;
    load_tile(0, 0);

    for (int it = 0; it < nIter; ++it) {
        if (it + 1 < nIter) {
            load_tile((it + 1) & 1, (it + 1) * BK);
            cp_wait<1>();
        } else {
            cp_wait<0>();
        }
        __syncthreads();
        const int buf = it & 1;
#pragma unroll
        for (int ks = 0; ks < BK / 8; ks++) {
            uint32_t af[MI][4];
#pragma unroll
            for (int mi = 0; mi < MI; mi++) {
                int mrow = mB + mi * 16 + g;
                af[mi][0] = __float_as_uint(As[buf][mrow    ][ks * 8 + t    ]);
                af[mi][1] = __float_as_uint(As[buf][mrow + 8][ks * 8 + t    ]);
                af[mi][2] = __float_as_uint(As[buf][mrow    ][ks * 8 + t + 4]);
                af[mi][3] = __float_as_uint(As[buf][mrow + 8][ks * 8 + t + 4]);
            }
            uint32_t bf[NI][2];
#pragma unroll
            for (int ni = 0; ni < NI; ni++) {
                int ncol = nB + ni * 8 + g;
                if (!TRANSB) {
                    bf[ni][0] = __float_as_uint(Bs[buf][ncol][ks * 8 + t    ]);
                    bf[ni][1] = __float_as_uint(Bs[buf][ncol][ks * 8 + t + 4]);
                } else {
                    bf[ni][0] = __float_as_uint(Bs[buf][ks * 8 + t    ][ncol]);
                    bf[ni][1] = __float_as_uint(Bs[buf][ks * 8 + t + 4][ncol]);
                }
            }
#pragma unroll
            for (int mi = 0; mi < MI; mi++)
#pragma unroll
                for (int ni = 0; ni < NI; ni++)
                    mma_tf32(acc[mi][ni], af[mi], bf[ni]);
        }
        __syncthreads();
    }

    // epilogue
#pragma unroll
    for (int mi = 0; mi < MI; mi++) {
        int r0 = m0 + mB + mi * 16 + g;
        int r1 = r0 + 8;
#pragma unroll
        for (int ni = 0; ni < NI; ni++) {
            int c = n0 + nB + ni * 8 + 2 * t;
            float v[4];
#pragma unroll
            for (int r = 0; r < 4; r++) v[r] = acc[mi][ni][r] * alpha;
            if (bias) {
                float b0 = bias[c], b1 = bias[c + 1];
                v[0] += b0; v[1] += b1; v[2] += b0; v[3] += b1;
            }
            if (ACT == 1) {
#pragma unroll
                for (int r = 0; r < 4; r++)
                    v[r] = 0.5f * v[r] * (1.f + erff(v[r] * 0.70710678118654752f));
            }
            if (resid) {
                const float* rp0 = resid + (size_t)zb * strCb + (size_t)zh * strCh;
                v[0] += rp0[(size_t)r0 * ldc + c];
                v[1] += rp0[(size_t)r0 * ldc + c + 1];
                v[2] += rp0[(size_t)r1 * ldc + c];
                v[3] += rp0[(size_t)r1 * ldc + c + 1];
            }
            *(float2*)&Cb[(size_t)r0 * ldc + c] = make_float2(v[0], v[1]);
            *(float2*)&Cb[(size_t)r1 * ldc + c] = make_float2(v[2], v[3]);
        }
    }
}

// ---------------- LayerNorm over DIM=768, one block per row ----------------
__global__ void ln_kernel(const float* __restrict__ x, const float* __restrict__ w,
                          const float* __restrict__ b, float* __restrict__ out) {
    int row = blockIdx.x;
    const float* xr = x + (size_t)row * DIM;
    float* orow = out + (size_t)row * DIM;
    float v[3];
    float s = 0.f, ss = 0.f;
#pragma unroll
    for (int i = 0; i < 3; i++) {
        v[i] = xr[threadIdx.x + i * 256];
        s += v[i]; ss += v[i] * v[i];
    }
    __shared__ float red0[8], red1[8];
    int lane = threadIdx.x & 31, wp = threadIdx.x >> 5;
#pragma unroll
    for (int o = 16; o; o >>= 1) {
        s  += __shfl_xor_sync(0xffffffffu, s, o);
        ss += __shfl_xor_sync(0xffffffffu, ss, o);
    }
    if (lane == 0) { red0[wp] = s; red1[wp] = ss; }
    __syncthreads();
    s = 0.f; ss = 0.f;
#pragma unroll
    for (int i = 0; i < 8; i++) { s += red0[i]; ss += red1[i]; }
    float mean = s * (1.f / DIM);
    float var  = ss * (1.f / DIM) - mean * mean;
    float inv  = rsqrtf(var + EPSI);
#pragma unroll
    for (int i = 0; i < 3; i++) {
        int c = threadIdx.x + i * 256;
        orow[c] = (v[i] - mean) * inv * w[c] + b[c];
    }
}

// ---------------- per-head LN: one warp per 64-elem chunk (in-place) -------
__global__ void head_ln_kernel(float* __restrict__ qkv, const float* __restrict__ w,
                               const float* __restrict__ b, size_t nchunks) {
    size_t warp = ((size_t)blockIdx.x * blockDim.x + threadIdx.x) >> 5;
    int lane = threadIdx.x & 31;
    if (warp >= nchunks) return;
    float* ptr = qkv + warp * 64;
    float x0 = ptr[lane], x1 = ptr[lane + 32];
    float s = x0 + x1, ss = x0 * x0 + x1 * x1;
#pragma unroll
    for (int o = 16; o; o >>= 1) {
        s  += __shfl_xor_sync(0xffffffffu, s, o);
        ss += __shfl_xor_sync(0xffffffffu, ss, o);
    }
    float mean = s * (1.f / 64.f);
    float var  = ss * (1.f / 64.f) - mean * mean;
    float inv  = rsqrtf(var + EPSI);
    ptr[lane]      = (x0 - mean) * inv * w[lane]      + b[lane];
    ptr[lane + 32] = (x1 - mean) * inv * w[lane + 32] + b[lane + 32];
}

// ---------------- row softmax over 1024, one block per row -----------------
__global__ void softmax_kernel(float* __restrict__ S) {
    size_t row = blockIdx.x;
    float* r = S + row * SEQ;
    float v[4];
    float mx = -1e30f;
#pragma unroll
    for (int i = 0; i < 4; i++) { v[i] = r[threadIdx.x + i * 256]; mx = fmaxf(mx, v[i]); }
    __shared__ float red[8];
    int lane = threadIdx.x & 31, wp = threadIdx.x >> 5;
#pragma unroll
    for (int o = 16; o; o >>= 1) mx = fmaxf(mx, __shfl_xor_sync(0xffffffffu, mx, o));
    if (lane == 0) red[wp] = mx;
    __syncthreads();
    mx = red[0];
#pragma unroll
    for (int i = 1; i < 8; i++) mx = fmaxf(mx, red[i]);
    float s = 0.f;
#pragma unroll
    for (int i = 0; i < 4; i++) { v[i] = __expf(v[i] - mx); s += v[i]; }
#pragma unroll
    for (int o = 16; o; o >>= 1) s += __shfl_xor_sync(0xffffffffu, s, o);
    __syncthreads();
    if (lane == 0) red[wp] = s;
    __syncthreads();
    s = 0.f;
#pragma unroll
    for (int i = 0; i < 8; i++) s += red[i];
    float inv = 1.f / s;
#pragma unroll
    for (int i = 0; i < 4; i++) r[threadIdx.x + i * 256] = v[i] * inv;
}

// ------- residual: res[dir] = xn[dir] + p[other] + remap(q[other]) ---------
__global__ void residual_kernel(const float* __restrict__ xn, const float* __restrict__ p,
                                const float* __restrict__ qkv, float* __restrict__ res)
{
    const size_t BNC = (size_t)BATCH * SEQ * DIM;
    size_t idx = (size_t)blockIdx.x * 256 + threadIdx.x;
    if (idx >= 2 * BNC) return;
    int dir = (int)(idx / BNC);
    size_t rem = idx - (size_t)dir * BNC;
    int b = (int)(rem / (SEQ * DIM));
    int t = (int)(rem % (SEQ * DIM));
    int other = 1 - dir;
    int h  = t >> 16;
    int r2 = t & 65535;
    int n2 = r2 >> 6;
    int d  = r2 & 63;
    float qv = qkv[((size_t)(other * BATCH + b) * SEQ + n2) * QKVC + h * HD + d];
    res[idx] = xn[idx] + p[(size_t)other * BNC + rem] + qv;
}

// ---------------------------------------------------------------------------
extern "C" void kernel_launch(void* const* d_in, const int* in_sizes, int n_in,
                              void* d_out, int out_size) {
    const float* before  = (const float*)d_in[0];
    const float* after   = (const float*)d_in[1];
    const float* norm1_w = (const float*)d_in[2];
    const float* norm1_b = (const float*)d_in[3];
    const float* qkv_w   = (const float*)d_in[4];
    const float* hln_w   = (const float*)d_in[5];
    const float* hln_b   = (const float*)d_in[6];
    const float* proj_w  = (const float*)d_in[7];
    const float* proj_b  = (const float*)d_in[8];
    const float* norm2_w = (const float*)d_in[9];
    const float* norm2_b = (const float*)d_in[10];
    const float* fc1_w   = (const float*)d_in[11];
    const float* fc1_b   = (const float*)d_in[12];
    const float* fc2_w   = (const float*)d_in[13];
    const float* fc2_b   = (const float*)d_in[14];
    float* out = (float*)d_out;

    float *xn, *qkv, *S, *ctx, *p, *res, *ln2, *hbuf;
    cudaGetSymbolAddress((void**)&xn,  g_xn);
    cudaGetSymbolAddress((void**)&qkv, g_qkv);
    cudaGetSymbolAddress((void**)&S,   g_S);
    cudaGetSymbolAddress((void**)&ctx, g_ctx);
    cudaGetSymbolAddress((void**)&p,   g_p);
    cudaGetSymbolAddress((void**)&res, g_res);
    cudaGetSymbolAddress((void**)&ln2, g_ln2);
    cudaGetSymbolAddress((void**)&hbuf, g_h);

    const size_t BNC = (size_t)BATCH * SEQ * DIM;
    const int ROWS1 = BATCH * SEQ;          // 8192
    const int ROWS2 = 2 * ROWS1;            // 16384
    const long long LL0 = 0;

    // 1. norm1 on both streams
    ln_kernel<<<ROWS1, 256>>>(before, norm1_w, norm1_b, xn);
    ln_kernel<<<ROWS1, 256>>>(after,  norm1_w, norm1_b, xn + BNC);

    // 2. fused-stream QKV GEMM
    mma_gemm<128,128,16,64,32,0,0><<<dim3(QKVC/128, ROWS2/128, 1), 256>>>(
        xn, DIM, LL0, LL0, qkv_w, DIM, LL0, LL0, nullptr, nullptr,
        qkv, QKVC, LL0, LL0, DIM, 1, 1.f);

    // 3. per-head LN (in place)
    {
        size_t nchunks = (size_t)ROWS2 * QKVC / 64;
        int blocks = (int)((nchunks * 32 + 255) / 256);
        head_ln_kernel<<<blocks, 256>>>(qkv, hln_w, hln_b, nchunks);
    }

    // 4. cross attention, both directions
    for (int dir = 0; dir < 2; dir++) {
        const float* qbase = qkv + (size_t)dir * BATCH * SEQ * QKVC;
        const float* kbase = qkv + (size_t)(1 - dir) * BATCH * SEQ * QKVC + DIM;
        const float* vbase = qkv + (size_t)(1 - dir) * BATCH * SEQ * QKVC + 2 * DIM;
        // S = 0.125 * Q @ K^T   (batched over 96 b*h)
        mma_gemm<128,128,16,64,32,0,0><<<dim3(SEQ/128, SEQ/128, BATCH*NHEAD), 256>>>(
            qbase, QKVC, (long long)SEQ * QKVC, (long long)HD,
            kbase, QKVC, (long long)SEQ * QKVC, (long long)HD,
            nullptr, nullptr,
            S, SEQ, (long long)NHEAD * SEQ * SEQ, (long long)SEQ * SEQ,
            HD, NHEAD, 0.125f);
        softmax_kernel<<<BATCH * NHEAD * SEQ, 256>>>(S);
        // ctx = P @ V (TRANSB: B is K x N row-major with ldb=QKVC)
        mma_gemm<128,64,16,32,32,1,0><<<dim3(1, SEQ/128, BATCH*NHEAD), 256>>>(
            S, SEQ, (long long)NHEAD * SEQ * SEQ, (long long)SEQ * SEQ,
            vbase, QKVC, (long long)SEQ * QKVC, (long long)HD,
            nullptr, nullptr,
            ctx + (size_t)dir * BNC, DIM, (long long)SEQ * DIM, (long long)HD,
            SEQ, NHEAD, 1.f);
    }

    // 5. output projection (both streams)
    mma_gemm<128,128,16,64,32,0,0><<<dim3(DIM/128, ROWS2/128, 1), 256>>>(
        ctx, DIM, LL0, LL0, proj_w, DIM, LL0, LL0, proj_b, nullptr,
        p, DIM, LL0, LL0, DIM, 1, 1.f);

    // 6. attention residual with cross-stream swap + faithful q-remap
    residual_kernel<<<(int)((2 * BNC + 255) / 256), 256>>>(xn, p, qkv, res);

    // 7. norm2
    ln_kernel<<<ROWS2, 256>>>(res, norm2_w, norm2_b, ln2);

    // 8. MLP: fc1 + exact GELU fused
    mma_gemm<128,128,16,64,32,0,1><<<dim3(HIDDEN/128, ROWS2/128, 1), 256>>>(
        ln2, DIM, LL0, LL0, fc1_w, DIM, LL0, LL0, fc1_b, nullptr,
        hbuf, HIDDEN, LL0, LL0, DIM, 1, 1.f);

    // 9. fc2 + bias + residual, straight into d_out
    mma_gemm<128,128,16,64,32,0,0><<<dim3(DIM/128, ROWS2/128, 1), 256>>>(
        hbuf, HIDDEN, LL0, LL0, fc2_w, HIDDEN, LL0, LL0, fc2_b, res,
        out, DIM, LL0, LL0, HIDDEN, 1, 1.f);
}

// round 3
// speedup vs baseline: 3.4536x; 1.1612x over previous
#include <cuda_runtime.h>
#include <math.h>
#include <stdint.h>

#define BATCH 8
#define SEQ 1024
#define DIM 768
#define NHEAD 12
#define HD 64
#define QKVC 2304
#define HIDDEN 3072
#define EPSI 1e-5f

// ---------------- scratch (device globals: allocation-free contract) --------
__device__ float g_xn [2ull*BATCH*SEQ*DIM];
__device__ float g_qkv[2ull*BATCH*SEQ*QKVC];
__device__ float g_ctx[2ull*BATCH*SEQ*DIM];
__device__ float g_p  [2ull*BATCH*SEQ*DIM];
__device__ float g_res[2ull*BATCH*SEQ*DIM];
__device__ float g_ln2[2ull*BATCH*SEQ*DIM];
__device__ float g_h  [2ull*BATCH*SEQ*HIDDEN];

// ---------------- async copy helpers ---------------------------------------
__device__ __forceinline__ void cp_async16(uint32_t smem, const void* g) {
    asm volatile("cp.async.cg.shared.global [%0], [%1], 16;" :: "r"(smem), "l"(g));
}
__device__ __forceinline__ void cp_commit() {
    asm volatile("cp.async.commit_group;");
}
template<int N> __device__ __forceinline__ void cp_wait() {
    asm volatile("cp.async.wait_group %0;" :: "n"(N));
}
__device__ __forceinline__ uint32_t smem_u32(const void* p) {
    return (uint32_t)__cvta_generic_to_shared(p);
}
__device__ __forceinline__ uint32_t as_u(float f) { return __float_as_uint(f); }

// ---------------- m16n8k8 tf32 mma -----------------------------------------
__device__ __forceinline__ void mma_tf32(float* c, const uint32_t* a, const uint32_t* b) {
    asm volatile(
        "mma.sync.aligned.m16n8k8.row.col.f32.tf32.tf32.f32 "
        "{%0,%1,%2,%3}, {%4,%5,%6,%7}, {%8,%9}, {%0,%1,%2,%3};"
        : "+f"(c[0]), "+f"(c[1]), "+f"(c[2]), "+f"(c[3])
        : "r"(a[0]), "r"(a[1]), "r"(a[2]), "r"(a[3]), "r"(b[0]), "r"(b[1]));
}

// ================= fused flash cross-attention ==============================
// grid (SEQ/128, BATCH*NHEAD, 2dirs), 256 threads (8 warps x 16 q-rows).
// ctx[dir] = softmax(0.125 * Q[dir] @ K[1-dir]^T) @ V[1-dir]
#define QT 128
#define KT 64

struct FlashSmem {
    float Q[QT][68];
    float K[2][KT][68];
    float V[2][KT][72];
    float P[QT][72];
};

__global__ void __launch_bounds__(256)
flash_attn_kernel(const float* __restrict__ qkv, float* __restrict__ ctx)
{
    extern __shared__ char smraw[];
    FlashSmem& sm = *reinterpret_cast<FlashSmem*>(smraw);
    const int tid  = threadIdx.x;
    const int lane = tid & 31, w = tid >> 5;
    const int g = lane >> 2, t = lane & 3;
    const int mB = w * 16;

    const int q0  = blockIdx.x * QT;
    const int bh  = blockIdx.y;
    const int b   = bh / NHEAD, h = bh - b * NHEAD;
    const int dir = blockIdx.z;

    const float* qb = qkv + ((size_t)(dir * BATCH + b) * SEQ) * QKVC + h * HD;
    const float* kb = qkv + ((size_t)((1 - dir) * BATCH + b) * SEQ) * QKVC + DIM + h * HD;
    const float* vb = kb + DIM;   // V is +2*DIM from base

    // group 0: Q tile + K0 + V0
    for (int l = tid; l < QT * 16; l += 256) {
        int r = l >> 4, c = (l & 15) * 4;
        cp_async16(smem_u32(&sm.Q[r][c]), qb + (size_t)(q0 + r) * QKVC + c);
    }
    for (int l = tid; l < KT * 16; l += 256) {
        int r = l >> 4, c = (l & 15) * 4;
        cp_async16(smem_u32(&sm.K[0][r][c]), kb + (size_t)r * QKVC + c);
        cp_async16(smem_u32(&sm.V[0][r][c]), vb + (size_t)r * QKVC + c);
    }
    cp_commit();

    float m0 = -1e30f, m1 = -1e30f, l0 = 0.f, l1 = 0.f;
    float O[8][4] = {};

    const int NIT = SEQ / KT;    // 16
    for (int it = 0; it < NIT; ++it) {
        if (it + 1 < NIT) {
            const int nb = (it + 1) & 1;
            const int kv = (it + 1) * KT;
            for (int l = tid; l < KT * 16; l += 256) {
                int r = l >> 4, c = (l & 15) * 4;
                cp_async16(smem_u32(&sm.K[nb][r][c]), kb + (size_t)(kv + r) * QKVC + c);
                cp_async16(smem_u32(&sm.V[nb][r][c]), vb + (size_t)(kv + r) * QKVC + c);
            }
            cp_commit();
            cp_wait<1>();
        } else {
            cp_wait<0>();
        }
        __syncthreads();
        const int buf = it & 1;

        // ---- S = Q @ K^T (warp: 16 q-rows x 64 kv-cols) ----
        float sf[8][4] = {};
#pragma unroll
        for (int ks = 0; ks < 8; ks++) {
            uint32_t af[4];
            af[0] = as_u(sm.Q[mB + g    ][ks * 8 + t    ]);
            af[1] = as_u(sm.Q[mB + g + 8][ks * 8 + t    ]);
            af[2] = as_u(sm.Q[mB + g    ][ks * 8 + t + 4]);
            af[3] = as_u(sm.Q[mB + g + 8][ks * 8 + t + 4]);
#pragma unroll
            for (int ni = 0; ni < 8; ni++) {
                uint32_t bf[2] = { as_u(sm.K[buf][ni * 8 + g][ks * 8 + t    ]),
                                   as_u(sm.K[buf][ni * 8 + g][ks * 8 + t + 4]) };
                mma_tf32(sf[ni], af, bf);
            }
        }

        // ---- online softmax (rows g and g+8 per thread) ----
        float mx0 = -1e30f, mx1 = -1e30f;
#pragma unroll
        for (int ni = 0; ni < 8; ni++) {
#pragma unroll
            for (int c = 0; c < 4; c++) sf[ni][c] *= 0.125f;
            mx0 = fmaxf(mx0, fmaxf(sf[ni][0], sf[ni][1]));
            mx1 = fmaxf(mx1, fmaxf(sf[ni][2], sf[ni][3]));
        }
        mx0 = fmaxf(mx0, __shfl_xor_sync(0xffffffffu, mx0, 1));
        mx0 = fmaxf(mx0, __shfl_xor_sync(0xffffffffu, mx0, 2));
        mx1 = fmaxf(mx1, __shfl_xor_sync(0xffffffffu, mx1, 1));
        mx1 = fmaxf(mx1, __shfl_xor_sync(0xffffffffu, mx1, 2));
        const float nm0 = fmaxf(m0, mx0), nm1 = fmaxf(m1, mx1);
        const float a0 = __expf(m0 - nm0), a1 = __expf(m1 - nm1);
        m0 = nm0; m1 = nm1;

        float s0 = 0.f, s1 = 0.f;
#pragma unroll
        for (int ni = 0; ni < 8; ni++) {
            sf[ni][0] = __expf(sf[ni][0] - m0);
            sf[ni][1] = __expf(sf[ni][1] - m0);
            sf[ni][2] = __expf(sf[ni][2] - m1);
            sf[ni][3] = __expf(sf[ni][3] - m1);
            s0 += sf[ni][0] + sf[ni][1];
            s1 += sf[ni][2] + sf[ni][3];
            *(float2*)&sm.P[mB + g    ][ni * 8 + 2 * t] = make_float2(sf[ni][0], sf[ni][1]);
            *(float2*)&sm.P[mB + g + 8][ni * 8 + 2 * t] = make_float2(sf[ni][2], sf[ni][3]);
        }
        s0 += __shfl_xor_sync(0xffffffffu, s0, 1);
        s0 += __shfl_xor_sync(0xffffffffu, s0, 2);
        s1 += __shfl_xor_sync(0xffffffffu, s1, 1);
        s1 += __shfl_xor_sync(0xffffffffu, s1, 2);
        l0 = l0 * a0 + s0;
        l1 = l1 * a1 + s1;
#pragma unroll
        for (int ni = 0; ni < 8; ni++) {
            O[ni][0] *= a0; O[ni][1] *= a0;
            O[ni][2] *= a1; O[ni][3] *= a1;
        }
        __syncwarp();

        // ---- O += P @ V ----
#pragma unroll
        for (int ks = 0; ks < 8; ks++) {
            uint32_t af[4];
            af[0] = as_u(sm.P[mB + g    ][ks * 8 + t    ]);
            af[1] = as_u(sm.P[mB + g + 8][ks * 8 + t    ]);
            af[2] = as_u(sm.P[mB + g    ][ks * 8 + t + 4]);
            af[3] = as_u(sm.P[mB + g + 8][ks * 8 + t + 4]);
#pragma unroll
            for (int ni = 0; ni < 8; ni++) {
                uint32_t bf[2] = { as_u(sm.V[buf][ks * 8 + t    ][ni * 8 + g]),
                                   as_u(sm.V[buf][ks * 8 + t + 4][ni * 8 + g]) };
                mma_tf32(O[ni], af, bf);
            }
        }
        __syncthreads();   // protect K/V buffers before next prefetch
    }

    // ---- epilogue: normalize + store ----
    const float inv0 = 1.f / l0, inv1 = 1.f / l1;
    float* cbase = ctx + ((size_t)(dir * BATCH + b) * SEQ + q0 + mB) * DIM + h * HD;
#pragma unroll
    for (int ni = 0; ni < 8; ni++) {
        int c = ni * 8 + 2 * t;
        *(float2*)&cbase[(size_t)(g    ) * DIM + c] = make_float2(O[ni][0] * inv0, O[ni][1] * inv0);
        *(float2*)&cbase[(size_t)(g + 8) * DIM + c] = make_float2(O[ni][2] * inv1, O[ni][3] * inv1);
    }
}

// ---------------- universal tf32 tensor-core GEMM ---------------------------
// C = act(A @ W^T + bias) [+ resid].  A:(M,K) lda=K, W:(N,K) ldb=K.
template<int BM, int BN, int BK, int WM, int WN, int ACT>
__global__ void __launch_bounds__((BM/WM)*(BN/WN)*32)
mma_gemm(const float* __restrict__ A, const float* __restrict__ B,
         const float* __restrict__ bias, const float* __restrict__ resid,
         float* __restrict__ C, int K, int N)
{
    constexpr int NW = (BM/WM)*(BN/WN);
    constexpr int NT = NW * 32;
    constexpr int SA = BK + 4;
    constexpr int MI = WM / 16;
    constexpr int NI = WN / 8;

    __shared__ float As[2][BM][SA];
    __shared__ float Bs[2][BN][SA];

    const int tid  = threadIdx.x;
    const int lane = tid & 31;
    const int wid  = tid >> 5;
    const int g    = lane >> 2;
    const int t    = lane & 3;

    constexpr int WROWS = BM / WM;
    const int wr = wid % WROWS, wc = wid / WROWS;
    const int mB = wr * WM, nB = wc * WN;

    const int m0 = blockIdx.y * BM;
    const int n0 = blockIdx.x * BN;

    auto load_tile = [&](int bufi, int k0) {
        {
            const float* src = A + (size_t)m0 * K + k0;
            constexpr int TOT = BM * BK / 4;
#pragma unroll
            for (int l = tid; l < TOT; l += NT) {
                int row = l / (BK / 4), q = l % (BK / 4);
                cp_async16(smem_u32(&As[bufi][row][q * 4]), src + (size_t)row * K + q * 4);
            }
        }
        {
            const float* src = B + (size_t)n0 * K + k0;
            constexpr int TOT = BN * BK / 4;
#pragma unroll
            for (int l = tid; l < TOT; l += NT) {
                int row = l / (BK / 4), q = l % (BK / 4);
                cp_async16(smem_u32(&Bs[bufi][row][q * 4]), src + (size_t)row * K + q * 4);
            }
        }
        cp_commit();
    };

    float acc[MI][NI][4];
#pragma unroll
    for (int mi = 0; mi < MI; mi++)
#pragma unroll
        for (int ni = 0; ni < NI; ni++)
#pragma unroll
            for (int r = 0; r < 4; r++) acc[mi][ni][r] = 0.f;

    const int nIter = K / BK;
    load_tile(0, 0);

    for (int it = 0; it < nIter; ++it) {
        if (it + 1 < nIter) {
            load_tile((it + 1) & 1, (it + 1) * BK);
            cp_wait<1>();
        } else {
            cp_wait<0>();
        }
        __syncthreads();
        const int bufi = it & 1;
#pragma unroll
        for (int ks = 0; ks < BK / 8; ks++) {
            uint32_t af[MI][4];
#pragma unroll
            for (int mi = 0; mi < MI; mi++) {
                int mrow = mB + mi * 16 + g;
                af[mi][0] = as_u(As[bufi][mrow    ][ks * 8 + t    ]);
                af[mi][1] = as_u(As[bufi][mrow + 8][ks * 8 + t    ]);
                af[mi][2] = as_u(As[bufi][mrow    ][ks * 8 + t + 4]);
                af[mi][3] = as_u(As[bufi][mrow + 8][ks * 8 + t + 4]);
            }
            uint32_t bf[NI][2];
#pragma unroll
            for (int ni = 0; ni < NI; ni++) {
                int ncol = nB + ni * 8 + g;
                bf[ni][0] = as_u(Bs[bufi][ncol][ks * 8 + t    ]);
                bf[ni][1] = as_u(Bs[bufi][ncol][ks * 8 + t + 4]);
            }
#pragma unroll
            for (int mi = 0; mi < MI; mi++)
#pragma unroll
                for (int ni = 0; ni < NI; ni++)
                    mma_tf32(acc[mi][ni], af[mi], bf[ni]);
        }
        __syncthreads();
    }

#pragma unroll
    for (int mi = 0; mi < MI; mi++) {
        int r0 = m0 + mB + mi * 16 + g;
        int r1 = r0 + 8;
#pragma unroll
        for (int ni = 0; ni < NI; ni++) {
            int c = n0 + nB + ni * 8 + 2 * t;
            float v[4] = { acc[mi][ni][0], acc[mi][ni][1], acc[mi][ni][2], acc[mi][ni][3] };
            if (bias) {
                float b0 = bias[c], b1 = bias[c + 1];
                v[0] += b0; v[1] += b1; v[2] += b0; v[3] += b1;
            }
            if (ACT == 1) {
#pragma unroll
                for (int r = 0; r < 4; r++)
                    v[r] = 0.5f * v[r] * (1.f + erff(v[r] * 0.70710678118654752f));
            }
            if (resid) {
                v[0] += resid[(size_t)r0 * N + c];
                v[1] += resid[(size_t)r0 * N + c + 1];
                v[2] += resid[(size_t)r1 * N + c];
                v[3] += resid[(size_t)r1 * N + c + 1];
            }
            *(float2*)&C[(size_t)r0 * N + c] = make_float2(v[0], v[1]);
            *(float2*)&C[(size_t)r1 * N + c] = make_float2(v[2], v[3]);
        }
    }
}

// ---------------- LayerNorm over DIM=768, one block per row ----------------
__global__ void ln_kernel(const float* __restrict__ x, const float* __restrict__ w,
                          const float* __restrict__ b, float* __restrict__ out) {
    int row = blockIdx.x;
    const float* xr = x + (size_t)row * DIM;
    float* orow = out + (size_t)row * DIM;
    float v[3];
    float s = 0.f, ss = 0.f;
#pragma unroll
    for (int i = 0; i < 3; i++) {
        v[i] = xr[threadIdx.x + i * 256];
        s += v[i]; ss += v[i] * v[i];
    }
    __shared__ float red0[8], red1[8];
    int lane = threadIdx.x & 31, wp = threadIdx.x >> 5;
#pragma unroll
    for (int o = 16; o; o >>= 1) {
        s  += __shfl_xor_sync(0xffffffffu, s, o);
        ss += __shfl_xor_sync(0xffffffffu, ss, o);
    }
    if (lane == 0) { red0[wp] = s; red1[wp] = ss; }
    __syncthreads();
    s = 0.f; ss = 0.f;
#pragma unroll
    for (int i = 0; i < 8; i++) { s += red0[i]; ss += red1[i]; }
    float mean = s * (1.f / DIM);
    float var  = ss * (1.f / DIM) - mean * mean;
    float inv  = rsqrtf(var + EPSI);
#pragma unroll
    for (int i = 0; i < 3; i++) {
        int c = threadIdx.x + i * 256;
        orow[c] = (v[i] - mean) * inv * w[c] + b[c];
    }
}

// ---------------- per-head LN: one warp per 64-elem chunk (in-place) -------
__global__ void head_ln_kernel(float* __restrict__ qkv, const float* __restrict__ w,
                               const float* __restrict__ b, size_t nchunks) {
    size_t warp = ((size_t)blockIdx.x * blockDim.x + threadIdx.x) >> 5;
    int lane = threadIdx.x & 31;
    if (warp >= nchunks) return;
    float* ptr = qkv + warp * 64;
    float x0 = ptr[lane], x1 = ptr[lane + 32];
    float s = x0 + x1, ss = x0 * x0 + x1 * x1;
#pragma unroll
    for (int o = 16; o; o >>= 1) {
        s  += __shfl_xor_sync(0xffffffffu, s, o);
        ss += __shfl_xor_sync(0xffffffffu, ss, o);
    }
    float mean = s * (1.f / 64.f);
    float var  = ss * (1.f / 64.f) - mean * mean;
    float inv  = rsqrtf(var + EPSI);
    ptr[lane]      = (x0 - mean) * inv * w[lane]      + b[lane];
    ptr[lane + 32] = (x1 - mean) * inv * w[lane + 32] + b[lane + 32];
}

// ------- residual: res[dir] = xn[dir] + p[other] + remap(q[other]) ---------
__global__ void residual_kernel(const float* __restrict__ xn, const float* __restrict__ p,
                                const float* __restrict__ qkv, float* __restrict__ res)
{
    const size_t BNC = (size_t)BATCH * SEQ * DIM;
    size_t idx = (size_t)blockIdx.x * 256 + threadIdx.x;
    if (idx >= 2 * BNC) return;
    int dir = (int)(idx / BNC);
    size_t rem = idx - (size_t)dir * BNC;
    int b = (int)(rem / (SEQ * DIM));
    int t = (int)(rem % (SEQ * DIM));
    int other = 1 - dir;
    int h  = t >> 16;
    int r2 = t & 65535;
    int n2 = r2 >> 6;
    int d  = r2 & 63;
    float qv = qkv[((size_t)(other * BATCH + b) * SEQ + n2) * QKVC + h * HD + d];
    res[idx] = xn[idx] + p[(size_t)other * BNC + rem] + qv;
}

// ---------------------------------------------------------------------------
extern "C" void kernel_launch(void* const* d_in, const int* in_sizes, int n_in,
                              void* d_out, int out_size) {
    const float* before  = (const float*)d_in[0];
    const float* after   = (const float*)d_in[1];
    const float* norm1_w = (const float*)d_in[2];
    const float* norm1_b = (const float*)d_in[3];
    const float* qkv_w   = (const float*)d_in[4];
    const float* hln_w   = (const float*)d_in[5];
    const float* hln_b   = (const float*)d_in[6];
    const float* proj_w  = (const float*)d_in[7];
    const float* proj_b  = (const float*)d_in[8];
    const float* norm2_w = (const float*)d_in[9];
    const float* norm2_b = (const float*)d_in[10];
    const float* fc1_w   = (const float*)d_in[11];
    const float* fc1_b   = (const float*)d_in[12];
    const float* fc2_w   = (const float*)d_in[13];
    const float* fc2_b   = (const float*)d_in[14];
    float* out = (float*)d_out;

    float *xn, *qkv, *ctx, *p, *res, *ln2, *hbuf;
    cudaGetSymbolAddress((void**)&xn,  g_xn);
    cudaGetSymbolAddress((void**)&qkv, g_qkv);
    cudaGetSymbolAddress((void**)&ctx, g_ctx);
    cudaGetSymbolAddress((void**)&p,   g_p);
    cudaGetSymbolAddress((void**)&res, g_res);
    cudaGetSymbolAddress((void**)&ln2, g_ln2);
    cudaGetSymbolAddress((void**)&hbuf, g_h);

    const size_t BNC = (size_t)BATCH * SEQ * DIM;
    const int ROWS1 = BATCH * SEQ;          // 8192
    const int ROWS2 = 2 * ROWS1;            // 16384

    // 1. norm1 on both streams
    ln_kernel<<<ROWS1, 256>>>(before, norm1_w, norm1_b, xn);
    ln_kernel<<<ROWS1, 256>>>(after,  norm1_w, norm1_b, xn + BNC);

    // 2. fused-stream QKV GEMM
    mma_gemm<128,128,16,64,32,0><<<dim3(QKVC/128, ROWS2/128), 256>>>(
        xn, qkv_w, nullptr, nullptr, qkv, DIM, QKVC);

    // 3. per-head LN (in place)
    {
        size_t nchunks = (size_t)ROWS2 * QKVC / 64;
        int blocks = (int)((nchunks * 32 + 255) / 256);
        head_ln_kernel<<<blocks, 256>>>(qkv, hln_w, hln_b, nchunks);
    }

    // 4. fused flash cross-attention (both directions, no S materialization)
    cudaFuncSetAttribute(flash_attn_kernel,
                         cudaFuncAttributeMaxDynamicSharedMemorySize,
                         (int)sizeof(FlashSmem));
    flash_attn_kernel<<<dim3(SEQ/QT, BATCH*NHEAD, 2), 256, sizeof(FlashSmem)>>>(qkv, ctx);

    // 5. output projection (both streams)
    mma_gemm<128,128,16,64,32,0><<<dim3(DIM/128, ROWS2/128), 256>>>(
        ctx, proj_w, proj_b, nullptr, p, DIM, DIM);

    // 6. attention residual with cross-stream swap + faithful q-remap
    residual_kernel<<<(int)((2 * BNC + 255) / 256), 256>>>(xn, p, qkv, res);

    // 7. norm2
    ln_kernel<<<ROWS2, 256>>>(res, norm2_w, norm2_b, ln2);

    // 8. MLP: fc1 + exact GELU fused
    mma_gemm<128,128,16,64,32,1><<<dim3(HIDDEN/128, ROWS2/128), 256>>>(
        ln2, fc1_w, fc1_b, nullptr, hbuf, DIM, HIDDEN);

    // 9. fc2 + bias + residual, straight into d_out
    mma_gemm<128,128,16,64,32,0><<<dim3(DIM/128, ROWS2/128), 256>>>(
        hbuf, fc2_w, fc2_b, res, out, HIDDEN, DIM);
}

// round 4
// speedup vs baseline: 3.4598x; 1.0018x over previous
#include <cuda_runtime.h>
#include <math.h>
#include <stdint.h>

#define BATCH 8
#define SEQ 1024
#define DIM 768
#define NHEAD 12
#define HD 64
#define QKVC 2304
#define HIDDEN 3072
#define EPSI 1e-5f

// ---------------- scratch (device globals: allocation-free contract) --------
__device__ float g_xn [2ull*BATCH*SEQ*DIM];
__device__ float g_qkv[2ull*BATCH*SEQ*QKVC];
__device__ float g_ctx[2ull*BATCH*SEQ*DIM];
__device__ float g_p  [2ull*BATCH*SEQ*DIM];
__device__ float g_res[2ull*BATCH*SEQ*DIM];
__device__ float g_ln2[2ull*BATCH*SEQ*DIM];
__device__ float g_h  [2ull*BATCH*SEQ*HIDDEN];

// ---------------- async copy helpers ---------------------------------------
__device__ __forceinline__ void cp_async16(uint32_t smem, const void* g) {
    asm volatile("cp.async.cg.shared.global [%0], [%1], 16;" :: "r"(smem), "l"(g));
}
__device__ __forceinline__ void cp_commit() {
    asm volatile("cp.async.commit_group;");
}
template<int N> __device__ __forceinline__ void cp_wait() {
    asm volatile("cp.async.wait_group %0;" :: "n"(N));
}
__device__ __forceinline__ uint32_t smem_u32(const void* p) {
    return (uint32_t)__cvta_generic_to_shared(p);
}
__device__ __forceinline__ uint32_t as_u(float f) { return __float_as_uint(f); }

// ---------------- m16n8k8 tf32 mma -----------------------------------------
__device__ __forceinline__ void mma_tf32(float* c, const uint32_t* a, const uint32_t* b) {
    asm volatile(
        "mma.sync.aligned.m16n8k8.row.col.f32.tf32.tf32.f32 "
        "{%0,%1,%2,%3}, {%4,%5,%6,%7}, {%8,%9}, {%0,%1,%2,%3};"
        : "+f"(c[0]), "+f"(c[1]), "+f"(c[2]), "+f"(c[3])
        : "r"(a[0]), "r"(a[1]), "r"(a[2]), "r"(a[3]), "r"(b[0]), "r"(b[1]));
}

// ================= fused flash cross-attention ==============================
// grid (SEQ/128, BATCH*NHEAD, 2dirs), 256 threads (8 warps x 16 q-rows).
// ctx[dir] = softmax(0.125 * Q[dir] @ K[1-dir]^T) @ V[1-dir]
#define QT 128
#define KT 64

struct FlashSmem {
    float Q[QT][68];
    float K[2][KT][68];
    float V[2][KT][72];
    float P[QT][72];
};

__global__ void __launch_bounds__(256)
flash_attn_kernel(const float* __restrict__ qkv, float* __restrict__ ctx)
{
    extern __shared__ char smraw[];
    FlashSmem& sm = *reinterpret_cast<FlashSmem*>(smraw);
    const int tid  = threadIdx.x;
    const int lane = tid & 31, w = tid >> 5;
    const int g = lane >> 2, t = lane & 3;
    const int mB = w * 16;

    const int q0  = blockIdx.x * QT;
    const int bh  = blockIdx.y;
    const int b   = bh / NHEAD, h = bh - b * NHEAD;
    const int dir = blockIdx.z;

    const float* qb = qkv + ((size_t)(dir * BATCH + b) * SEQ) * QKVC + h * HD;
    const float* kb = qkv + ((size_t)((1 - dir) * BATCH + b) * SEQ) * QKVC + DIM + h * HD;
    const float* vb = kb + DIM;   // V is +2*DIM from base

    // group 0: Q tile + K0 + V0
    for (int l = tid; l < QT * 16; l += 256) {
        int r = l >> 4, c = (l & 15) * 4;
        cp_async16(smem_u32(&sm.Q[r][c]), qb + (size_t)(q0 + r) * QKVC + c);
    }
    for (int l = tid; l < KT * 16; l += 256) {
        int r = l >> 4, c = (l & 15) * 4;
        cp_async16(smem_u32(&sm.K[0][r][c]), kb + (size_t)r * QKVC + c);
        cp_async16(smem_u32(&sm.V[0][r][c]), vb + (size_t)r * QKVC + c);
    }
    cp_commit();

    float m0 = -1e30f, m1 = -1e30f, l0 = 0.f, l1 = 0.f;
    float O[8][4] = {};

    const int NIT = SEQ / KT;    // 16
    for (int it = 0; it < NIT; ++it) {
        if (it + 1 < NIT) {
            const int nb = (it + 1) & 1;
            const int kv = (it + 1) * KT;
            for (int l = tid; l < KT * 16; l += 256) {
                int r = l >> 4, c = (l & 15) * 4;
                cp_async16(smem_u32(&sm.K[nb][r][c]), kb + (size_t)(kv + r) * QKVC + c);
                cp_async16(smem_u32(&sm.V[nb][r][c]), vb + (size_t)(kv + r) * QKVC + c);
            }
            cp_commit();
            cp_wait<1>();
        } else {
            cp_wait<0>();
        }
        __syncthreads();
        const int buf = it & 1;

        // ---- S = Q @ K^T (warp: 16 q-rows x 64 kv-cols) ----
        float sf[8][4] = {};
#pragma unroll
        for (int ks = 0; ks < 8; ks++) {
            uint32_t af[4];
            af[0] = as_u(sm.Q[mB + g    ][ks * 8 + t    ]);
            af[1] = as_u(sm.Q[mB + g + 8][ks * 8 + t    ]);
            af[2] = as_u(sm.Q[mB + g    ][ks * 8 + t + 4]);
            af[3] = as_u(sm.Q[mB + g + 8][ks * 8 + t + 4]);
#pragma unroll
            for (int ni = 0; ni < 8; ni++) {
                uint32_t bf[2] = { as_u(sm.K[buf][ni * 8 + g][ks * 8 + t    ]),
                                   as_u(sm.K[buf][ni * 8 + g][ks * 8 + t + 4]) };
                mma_tf32(sf[ni], af, bf);
            }
        }

        // ---- online softmax (rows g and g+8 per thread) ----
        float mx0 = -1e30f, mx1 = -1e30f;
#pragma unroll
        for (int ni = 0; ni < 8; ni++) {
#pragma unroll
            for (int c = 0; c < 4; c++) sf[ni][c] *= 0.125f;
            mx0 = fmaxf(mx0, fmaxf(sf[ni][0], sf[ni][1]));
            mx1 = fmaxf(mx1, fmaxf(sf[ni][2], sf[ni][3]));
        }
        mx0 = fmaxf(mx0, __shfl_xor_sync(0xffffffffu, mx0, 1));
        mx0 = fmaxf(mx0, __shfl_xor_sync(0xffffffffu, mx0, 2));
        mx1 = fmaxf(mx1, __shfl_xor_sync(0xffffffffu, mx1, 1));
        mx1 = fmaxf(mx1, __shfl_xor_sync(0xffffffffu, mx1, 2));
        const float nm0 = fmaxf(m0, mx0), nm1 = fmaxf(m1, mx1);
        const float a0 = __expf(m0 - nm0), a1 = __expf(m1 - nm1);
        m0 = nm0; m1 = nm1;

        float s0 = 0.f, s1 = 0.f;
#pragma unroll
        for (int ni = 0; ni < 8; ni++) {
            sf[ni][0] = __expf(sf[ni][0] - m0);
            sf[ni][1] = __expf(sf[ni][1] - m0);
            sf[ni][2] = __expf(sf[ni][2] - m1);
            sf[ni][3] = __expf(sf[ni][3] - m1);
            s0 += sf[ni][0] + sf[ni][1];
            s1 += sf[ni][2] + sf[ni][3];
            *(float2*)&sm.P[mB + g    ][ni * 8 + 2 * t] = make_float2(sf[ni][0], sf[ni][1]);
            *(float2*)&sm.P[mB + g + 8][ni * 8 + 2 * t] = make_float2(sf[ni][2], sf[ni][3]);
        }
        s0 += __shfl_xor_sync(0xffffffffu, s0, 1);
        s0 += __shfl_xor_sync(0xffffffffu, s0, 2);
        s1 += __shfl_xor_sync(0xffffffffu, s1, 1);
        s1 += __shfl_xor_sync(0xffffffffu, s1, 2);
        l0 = l0 * a0 + s0;
        l1 = l1 * a1 + s1;
#pragma unroll
        for (int ni = 0; ni < 8; ni++) {
            O[ni][0] *= a0; O[ni][1] *= a0;
            O[ni][2] *= a1; O[ni][3] *= a1;
        }
        __syncwarp();

        // ---- O += P @ V ----
#pragma unroll
        for (int ks = 0; ks < 8; ks++) {
            uint32_t af[4];
            af[0] = as_u(sm.P[mB + g    ][ks * 8 + t    ]);
            af[1] = as_u(sm.P[mB + g + 8][ks * 8 + t    ]);
            af[2] = as_u(sm.P[mB + g    ][ks * 8 + t + 4]);
            af[3] = as_u(sm.P[mB + g + 8][ks * 8 + t + 4]);
#pragma unroll
            for (int ni = 0; ni < 8; ni++) {
                uint32_t bf[2] = { as_u(sm.V[buf][ks * 8 + t    ][ni * 8 + g]),
                                   as_u(sm.V[buf][ks * 8 + t + 4][ni * 8 + g]) };
                mma_tf32(O[ni], af, bf);
            }
        }
        __syncthreads();   // protect K/V buffers before next prefetch
    }

    // ---- epilogue: normalize + store ----
    const float inv0 = 1.f / l0, inv1 = 1.f / l1;
    float* cbase = ctx + ((size_t)(dir * BATCH + b) * SEQ + q0 + mB) * DIM + h * HD;
#pragma unroll
    for (int ni = 0; ni < 8; ni++) {
        int c = ni * 8 + 2 * t;
        *(float2*)&cbase[(size_t)(g    ) * DIM + c] = make_float2(O[ni][0] * inv0, O[ni][1] * inv0);
        *(float2*)&cbase[(size_t)(g + 8) * DIM + c] = make_float2(O[ni][2] * inv1, O[ni][3] * inv1);
    }
}

// ---------------- universal tf32 tensor-core GEMM ---------------------------
// C = act(A @ W^T + bias) [+ resid].  A:(M,K) lda=K, W:(N,K) ldb=K.
template<int BM, int BN, int BK, int WM, int WN, int ACT>
__global__ void __launch_bounds__((BM/WM)*(BN/WN)*32)
mma_gemm(const float* __restrict__ A, const float* __restrict__ B,
         const float* __restrict__ bias, const float* __restrict__ resid,
         float* __restrict__ C, int K, int N)
{
    constexpr int NW = (BM/WM)*(BN/WN);
    constexpr int NT = NW * 32;
    constexpr int SA = BK + 4;
    constexpr int MI = WM / 16;
    constexpr int NI = WN / 8;

    __shared__ float As[2][BM][SA];
    __shared__ float Bs[2][BN][SA];

    const int tid  = threadIdx.x;
    const int lane = tid & 31;
    const int wid  = tid >> 5;
    const int g    = lane >> 2;
    const int t    = lane & 3;

    constexpr int WROWS = BM / WM;
    const int wr = wid % WROWS, wc = wid / WROWS;
    const int mB = wr * WM, nB = wc * WN;

    const int m0 = blockIdx.y * BM;
    const int n0 = blockIdx.x * BN;

    auto load_tile = [&](int bufi, int k0) {
        {
            const float* src = A + (size_t)m0 * K + k0;
            constexpr int TOT = BM * BK / 4;
#pragma unroll
            for (int l = tid; l < TOT; l += NT) {
                int row = l / (BK / 4), q = l % (BK / 4);
                cp_async16(smem_u32(&As[bufi][row][q * 4]), src + (size_t)row * K + q * 4);
            }
        }
        {
            const float* src = B + (size_t)n0 * K + k0;
            constexpr int TOT = BN * BK / 4;
#pragma unroll
            for (int l = tid; l < TOT; l += NT) {
                int row = l / (BK / 4), q = l % (BK / 4);
                cp_async16(smem_u32(&Bs[bufi][row][q * 4]), src + (size_t)row * K + q * 4);
            }
        }
        cp_commit();
    };

    float acc[MI][NI][4];
#pragma unroll
    for (int mi = 0; mi < MI; mi++)
#pragma unroll
        for (int ni = 0; ni < NI; ni++)
#pragma unroll
            for (int r = 0; r < 4; r++) acc[mi][ni][r] = 0.f;

    const int nIter = K / BK;
    load_tile(0, 0);

    for (int it = 0; it < nIter; ++it) {
        if (it + 1 < nIter) {
            load_tile((it + 1) & 1, (it + 1) * BK);
            cp_wait<1>();
        } else {
            cp_wait<0>();
        }
        __syncthreads();
        const int bufi = it & 1;
#pragma unroll
        for (int ks = 0; ks < BK / 8; ks++) {
            uint32_t af[MI][4];
#pragma unroll
            for (int mi = 0; mi < MI; mi++) {
                int mrow = mB + mi * 16 + g;
                af[mi][0] = as_u(As[bufi][mrow    ][ks * 8 + t    ]);
                af[mi][1] = as_u(As[bufi][mrow + 8][ks * 8 + t    ]);
                af[mi][2] = as_u(As[bufi][mrow    ][ks * 8 + t + 4]);
                af[mi][3] = as_u(As[bufi][mrow + 8][ks * 8 + t + 4]);
            }
            uint32_t bf[NI][2];
#pragma unroll
            for (int ni = 0; ni < NI; ni++) {
                int ncol = nB + ni * 8 + g;
                bf[ni][0] = as_u(Bs[bufi][ncol][ks * 8 + t    ]);
                bf[ni][1] = as_u(Bs[bufi][ncol][ks * 8 + t + 4]);
            }
#pragma unroll
            for (int mi = 0; mi < MI; mi++)
#pragma unroll
                for (int ni = 0; ni < NI; ni++)
                    mma_tf32(acc[mi][ni], af[mi], bf[ni]);
        }
        __syncthreads();
    }

#pragma unroll
    for (int mi = 0; mi < MI; mi++) {
        int r0 = m0 + mB + mi * 16 + g;
        int r1 = r0 + 8;
#pragma unroll
        for (int ni = 0; ni < NI; ni++) {
            int c = n0 + nB + ni * 8 + 2 * t;
            float v[4] = { acc[mi][ni][0], acc[mi][ni][1], acc[mi][ni][2], acc[mi][ni][3] };
            if (bias) {
                float b0 = bias[c], b1 = bias[c + 1];
                v[0] += b0; v[1] += b1; v[2] += b0; v[3] += b1;
            }
            if (ACT == 1) {
#pragma unroll
                for (int r = 0; r < 4; r++)
                    v[r] = 0.5f * v[r] * (1.f + erff(v[r] * 0.70710678118654752f));
            }
            if (resid) {
                v[0] += resid[(size_t)r0 * N + c];
                v[1] += resid[(size_t)r0 * N + c + 1];
                v[2] += resid[(size_t)r1 * N + c];
                v[3] += resid[(size_t)r1 * N + c + 1];
            }
            *(float2*)&C[(size_t)r0 * N + c] = make_float2(v[0], v[1]);
            *(float2*)&C[(size_t)r1 * N + c] = make_float2(v[2], v[3]);
        }
    }
}

// ---------------- LayerNorm over DIM=768, one block per row ----------------
__global__ void ln_kernel(const float* __restrict__ x, const float* __restrict__ w,
                          const float* __restrict__ b, float* __restrict__ out) {
    int row = blockIdx.x;
    const float* xr = x + (size_t)row * DIM;
    float* orow = out + (size_t)row * DIM;
    float v[3];
    float s = 0.f, ss = 0.f;
#pragma unroll
    for (int i = 0; i < 3; i++) {
        v[i] = xr[threadIdx.x + i * 256];
        s += v[i]; ss += v[i] * v[i];
    }
    __shared__ float red0[8], red1[8];
    int lane = threadIdx.x & 31, wp = threadIdx.x >> 5;
#pragma unroll
    for (int o = 16; o; o >>= 1) {
        s  += __shfl_xor_sync(0xffffffffu, s, o);
        ss += __shfl_xor_sync(0xffffffffu, ss, o);
    }
    if (lane == 0) { red0[wp] = s; red1[wp] = ss; }
    __syncthreads();
    s = 0.f; ss = 0.f;
#pragma unroll
    for (int i = 0; i < 8; i++) { s += red0[i]; ss += red1[i]; }
    float mean = s * (1.f / DIM);
    float var  = ss * (1.f / DIM) - mean * mean;
    float inv  = rsqrtf(var + EPSI);
#pragma unroll
    for (int i = 0; i < 3; i++) {
        int c = threadIdx.x + i * 256;
        orow[c] = (v[i] - mean) * inv * w[c] + b[c];
    }
}

// ---------------- per-head LN: one warp per 64-elem chunk (in-place) -------
__global__ void head_ln_kernel(float* __restrict__ qkv, const float* __restrict__ w,
                               const float* __restrict__ b, size_t nchunks) {
    size_t warp = ((size_t)blockIdx.x * blockDim.x + threadIdx.x) >> 5;
    int lane = threadIdx.x & 31;
    if (warp >= nchunks) return;
    float* ptr = qkv + warp * 64;
    float x0 = ptr[lane], x1 = ptr[lane + 32];
    float s = x0 + x1, ss = x0 * x0 + x1 * x1;
#pragma unroll
    for (int o = 16; o; o >>= 1) {
        s  += __shfl_xor_sync(0xffffffffu, s, o);
        ss += __shfl_xor_sync(0xffffffffu, ss, o);
    }
    float mean = s * (1.f / 64.f);
    float var  = ss * (1.f / 64.f) - mean * mean;
    float inv  = rsqrtf(var + EPSI);
    ptr[lane]      = (x0 - mean) * inv * w[lane]      + b[lane];
    ptr[lane + 32] = (x1 - mean) * inv * w[lane + 32] + b[lane + 32];
}

// ------- residual: res[dir] = xn[dir] + p[other] + remap(q[other]) ---------
__global__ void residual_kernel(const float* __restrict__ xn, const float* __restrict__ p,
                                const float* __restrict__ qkv, float* __restrict__ res)
{
    const size_t BNC = (size_t)BATCH * SEQ * DIM;
    size_t idx = (size_t)blockIdx.x * 256 + threadIdx.x;
    if (idx >= 2 * BNC) return;
    int dir = (int)(idx / BNC);
    size_t rem = idx - (size_t)dir * BNC;
    int b = (int)(rem / (SEQ * DIM));
    int t = (int)(rem % (SEQ * DIM));
    int other = 1 - dir;
    int h  = t >> 16;
    int r2 = t & 65535;
    int n2 = r2 >> 6;
    int d  = r2 & 63;
    float qv = qkv[((size_t)(other * BATCH + b) * SEQ + n2) * QKVC + h * HD + d];
    res[idx] = xn[idx] + p[(size_t)other * BNC + rem] + qv;
}

// ---------------------------------------------------------------------------
extern "C" void kernel_launch(void* const* d_in, const int* in_sizes, int n_in,
                              void* d_out, int out_size) {
    const float* before  = (const float*)d_in[0];
    const float* after   = (const float*)d_in[1];
    const float* norm1_w = (const float*)d_in[2];
    const float* norm1_b = (const float*)d_in[3];
    const float* qkv_w   = (const float*)d_in[4];
    const float* hln_w   = (const float*)d_in[5];
    const float* hln_b   = (const float*)d_in[6];
    const float* proj_w  = (const float*)d_in[7];
    const float* proj_b  = (const float*)d_in[8];
    const float* norm2_w = (const float*)d_in[9];
    const float* norm2_b = (const float*)d_in[10];
    const float* fc1_w   = (const float*)d_in[11];
    const float* fc1_b   = (const float*)d_in[12];
    const float* fc2_w   = (const float*)d_in[13];
    const float* fc2_b   = (const float*)d_in[14];
    float* out = (float*)d_out;

    float *xn, *qkv, *ctx, *p, *res, *ln2, *hbuf;
    cudaGetSymbolAddress((void**)&xn,  g_xn);
    cudaGetSymbolAddress((void**)&qkv, g_qkv);
    cudaGetSymbolAddress((void**)&ctx, g_ctx);
    cudaGetSymbolAddress((void**)&p,   g_p);
    cudaGetSymbolAddress((void**)&res, g_res);
    cudaGetSymbolAddress((void**)&ln2, g_ln2);
    cudaGetSymbolAddress((void**)&hbuf, g_h);

    const size_t BNC = (size_t)BATCH * SEQ * DIM;
    const int ROWS1 = BATCH * SEQ;          // 8192
    const int ROWS2 = 2 * ROWS1;            // 16384

    // 1. norm1 on both streams
    ln_kernel<<<ROWS1, 256>>>(before, norm1_w, norm1_b, xn);
    ln_kernel<<<ROWS1, 256>>>(after,  norm1_w, norm1_b, xn + BNC);

    // 2. fused-stream QKV GEMM
    mma_gemm<128,128,16,64,32,0><<<dim3(QKVC/128, ROWS2/128), 256>>>(
        xn, qkv_w, nullptr, nullptr, qkv, DIM, QKVC);

    // 3. per-head LN (in place)
    {
        size_t nchunks = (size_t)ROWS2 * QKVC / 64;
        int blocks = (int)((nchunks * 32 + 255) / 256);
        head_ln_kernel<<<blocks, 256>>>(qkv, hln_w, hln_b, nchunks);
    }

    // 4. fused flash cross-attention (both directions, no S materialization)
    cudaFuncSetAttribute(flash_attn_kernel,
                         cudaFuncAttributeMaxDynamicSharedMemorySize,
                         (int)sizeof(FlashSmem));
    flash_attn_kernel<<<dim3(SEQ/QT, BATCH*NHEAD, 2), 256, sizeof(FlashSmem)>>>(qkv, ctx);

    // 5. output projection (both streams)
    mma_gemm<128,128,16,64,32,0><<<dim3(DIM/128, ROWS2/128), 256>>>(
        ctx, proj_w, proj_b, nullptr, p, DIM, DIM);

    // 6. attention residual with cross-stream swap + faithful q-remap
    residual_kernel<<<(int)((2 * BNC + 255) / 256), 256>>>(xn, p, qkv, res);

    // 7. norm2
    ln_kernel<<<ROWS2, 256>>>(res, norm2_w, norm2_b, ln2);

    // 8. MLP: fc1 + exact GELU fused
    mma_gemm<128,128,16,64,32,1><<<dim3(HIDDEN/128, ROWS2/128), 256>>>(
        ln2, fc1_w, fc1_b, nullptr, hbuf, DIM, HIDDEN);

    // 9. fc2 + bias + residual, straight into d_out
    mma_gemm<128,128,16,64,32,0><<<dim3(DIM/128, ROWS2/128), 256>>>(
        hbuf, fc2_w, fc2_b, res, out, HIDDEN, DIM);
}

// round 7
// speedup vs baseline: 5.8133x; 1.6802x over previous
#include <cuda_runtime.h>
#include <cuda_fp16.h>
#include <math.h>
#include <stdint.h>

#define BATCH 8
#define SEQ 1024
#define DIM 768
#define NHEAD 12
#define HD 64
#define QKVC 2304
#define HIDDEN 3072
#define EPSI 1e-5f

// ---------------- scratch (device globals: allocation-free contract) --------
__device__ float  g_xn  [2ull*BATCH*SEQ*DIM];
__device__ float  g_qkv [2ull*BATCH*SEQ*QKVC];
__device__ float  g_p   [2ull*BATCH*SEQ*DIM];
__device__ float  g_res [2ull*BATCH*SEQ*DIM];
__device__ __half g_xn16 [2ull*BATCH*SEQ*DIM];
__device__ __half g_qkv16[2ull*BATCH*SEQ*QKVC];
__device__ __half g_vt   [2ull*BATCH*NHEAD*HD*SEQ];   // V transposed: [dir][b][h][d][kv]
__device__ __half g_ctx16[2ull*BATCH*SEQ*DIM];
__device__ __half g_ln216[2ull*BATCH*SEQ*DIM];
__device__ __half g_h16  [2ull*BATCH*SEQ*HIDDEN];
__device__ __half g_w16  [7077888];                   // qkv_w|proj_w|fc1_w|fc2_w

#define W16_QKV  0
#define W16_PROJ 1769472
#define W16_FC1  2359296
#define W16_FC2  4718592

// ---------------- async copy helpers ---------------------------------------
__device__ __forceinline__ void cp_async16(uint32_t smem, const void* g) {
    asm volatile("cp.async.cg.shared.global [%0], [%1], 16;" :: "r"(smem), "l"(g));
}
__device__ __forceinline__ void cp_commit() {
    asm volatile("cp.async.commit_group;");
}
template<int N> __device__ __forceinline__ void cp_wait() {
    asm volatile("cp.async.wait_group %0;" :: "n"(N));
}
__device__ __forceinline__ uint32_t smem_u32(const void* p) {
    return (uint32_t)__cvta_generic_to_shared(p);
}
__device__ __forceinline__ uint32_t ld32h(const __half* p) {   // aligned 32-bit load
    return *(const uint32_t*)p;
}

// ---------------- m16n8k16 fp16 mma (fp32 accum) ----------------------------
__device__ __forceinline__ void mma_f16(float* c, const uint32_t* a, const uint32_t* b) {
    asm volatile(
        "mma.sync.aligned.m16n8k16.row.col.f32.f16.f16.f32 "
        "{%0,%1,%2,%3}, {%4,%5,%6,%7}, {%8,%9}, {%0,%1,%2,%3};"
        : "+f"(c[0]), "+f"(c[1]), "+f"(c[2]), "+f"(c[3])
        : "r"(a[0]), "r"(a[1]), "r"(a[2]), "r"(a[3]), "r"(b[0]), "r"(b[1]));
}

// ---------------- fp32 -> fp16 elementwise convert --------------------------
__global__ void f2h_kernel(const float* __restrict__ x, __half* __restrict__ y, int n) {
    int i = (blockIdx.x * 256 + threadIdx.x) * 4;
    if (i >= n) return;
    float4 v = *(const float4*)&x[i];
    *(__half2*)&y[i]     = __floats2half2_rn(v.x, v.y);
    *(__half2*)&y[i + 2] = __floats2half2_rn(v.z, v.w);
}

// ================= dense fp16 tensor-core GEMM ==============================
// C = act(A @ W^T + bias) [+ resid].  A:(M,K) fp16, W:(N,K) fp16.
#define BM 128
#define BN 128
#define BK 32
#define SA 40   // smem row stride in halves (80B: 16B-aligned, conflict-free map)

template<int ACT, bool OUT_HALF, bool HAS_RES>
__global__ void __launch_bounds__(256)
hgemm(const __half* __restrict__ A, const __half* __restrict__ W,
      const float* __restrict__ bias, const float* __restrict__ resid,
      void* __restrict__ Cv, int K, int N)
{
    __shared__ __half As[2][BM][SA];
    __shared__ __half Bs[2][BN][SA];

    const int tid = threadIdx.x;
    const int lane = tid & 31, wid = tid >> 5;
    const int g = lane >> 2, t = lane & 3;
    const int wr = wid & 1, wc = wid >> 1;          // 2x4 warp grid: 64x32 tiles
    const int mB = wr * 64, nB = wc * 32;
    const int m0 = blockIdx.y * BM, n0 = blockIdx.x * BN;

    auto load_stage = [&](int buf, int k0) {
        const __half* aSrc = A + (size_t)m0 * K + k0;
#pragma unroll
        for (int i = 0; i < 2; i++) {                // 128 rows x 4 chunks / 256 thr
            int l = tid + i * 256;
            int r = l >> 2, q = l & 3;
            cp_async16(smem_u32(&As[buf][r][q * 8]), aSrc + (size_t)r * K + q * 8);
        }
        const __half* bSrc = W + (size_t)n0 * K + k0;
#pragma unroll
        for (int i = 0; i < 2; i++) {
            int l = tid + i * 256;
            int r = l >> 2, q = l & 3;
            cp_async16(smem_u32(&Bs[buf][r][q * 8]), bSrc + (size_t)r * K + q * 8);
        }
        cp_commit();
    };

    float acc[4][4][4];
#pragma unroll
    for (int mi = 0; mi < 4; mi++)
#pragma unroll
        for (int ni = 0; ni < 4; ni++)
#pragma unroll
            for (int r = 0; r < 4; r++) acc[mi][ni][r] = 0.f;

    const int nIter = K / BK;
    load_stage(0, 0);

    for (int it = 0; it < nIter; ++it) {
        if (it + 1 < nIter) {
            load_stage((it + 1) & 1, (it + 1) * BK);
            cp_wait<1>();
        } else {
            cp_wait<0>();
        }
        __syncthreads();
        const int buf = it & 1;
#pragma unroll
        for (int ks = 0; ks < 2; ks++) {             // two k16 slices in BK=32
            uint32_t af[4][4];
#pragma unroll
            for (int mi = 0; mi < 4; mi++) {
                int mr = mB + mi * 16 + g;
                int kc = ks * 16 + 2 * t;
                af[mi][0] = ld32h(&As[buf][mr    ][kc    ]);
                af[mi][1] = ld32h(&As[buf][mr + 8][kc    ]);
                af[mi][2] = ld32h(&As[buf][mr    ][kc + 8]);
                af[mi][3] = ld32h(&As[buf][mr + 8][kc + 8]);
            }
            uint32_t bf[4][2];
#pragma unroll
            for (int ni = 0; ni < 4; ni++) {
                int nc = nB + ni * 8 + g;
                int kc = ks * 16 + 2 * t;
                bf[ni][0] = ld32h(&Bs[buf][nc][kc    ]);
                bf[ni][1] = ld32h(&Bs[buf][nc][kc + 8]);
            }
#pragma unroll
            for (int mi = 0; mi < 4; mi++)
#pragma unroll
                for (int ni = 0; ni < 4; ni++)
                    mma_f16(acc[mi][ni], af[mi], bf[ni]);
        }
        __syncthreads();
    }

    // epilogue
#pragma unroll
    for (int mi = 0; mi < 4; mi++) {
        int r0 = m0 + mB + mi * 16 + g;
        int r1 = r0 + 8;
#pragma unroll
        for (int ni = 0; ni < 4; ni++) {
            int c = n0 + nB + ni * 8 + 2 * t;
            float v[4] = { acc[mi][ni][0], acc[mi][ni][1], acc[mi][ni][2], acc[mi][ni][3] };
            if (bias) {
                float b0 = bias[c], b1 = bias[c + 1];
                v[0] += b0; v[1] += b1; v[2] += b0; v[3] += b1;
            }
            if (ACT == 1) {
#pragma unroll
                for (int r = 0; r < 4; r++)
                    v[r] = 0.5f * v[r] * (1.f + erff(v[r] * 0.70710678118654752f));
            }
            if (HAS_RES) {
                v[0] += resid[(size_t)r0 * N + c];
                v[1] += resid[(size_t)r0 * N + c + 1];
                v[2] += resid[(size_t)r1 * N + c];
                v[3] += resid[(size_t)r1 * N + c + 1];
            }
            if (OUT_HALF) {
                __half* Ch = (__half*)Cv;
                *(__half2*)&Ch[(size_t)r0 * N + c] = __floats2half2_rn(v[0], v[1]);
                *(__half2*)&Ch[(size_t)r1 * N + c] = __floats2half2_rn(v[2], v[3]);
            } else {
                float* Cf = (float*)Cv;
                *(float2*)&Cf[(size_t)r0 * N + c] = make_float2(v[0], v[1]);
                *(float2*)&Cf[(size_t)r1 * N + c] = make_float2(v[2], v[3]);
            }
        }
    }
}

// ================= V transpose: qkv fp32 -> Vt fp16 [dbh][d][kv] ============
__global__ void vt_kernel(const float* __restrict__ qkv, __half* __restrict__ vt)
{
    __shared__ __half s[64][72];
    const int dbh = blockIdx.y;               // dir*96 + b*12 + h
    const int kv0 = blockIdx.x * 64;
    const int dir = dbh / 96, rem = dbh % 96;
    const int b = rem / NHEAD, h = rem % NHEAD;
    const int tid = threadIdx.x;
    const float* src = qkv + ((size_t)(dir * BATCH + b) * SEQ) * QKVC + 2 * DIM + h * HD;
    for (int l = tid; l < 64 * 64; l += 256) {
        int r = l >> 6, c = l & 63;           // r = kv-local, c = d (coalesced read)
        s[c][r] = __float2half(src[(size_t)(kv0 + r) * QKVC + c]);
    }
    __syncthreads();
    __half* dst = vt + (size_t)dbh * HD * SEQ + kv0;
    for (int l = tid; l < 64 * 64; l += 256) {
        int d = l >> 6, kk = l & 63;          // coalesced write
        dst[(size_t)d * SEQ + kk] = s[d][kk];
    }
}

// ================= fused fp16 flash cross-attention =========================
#define QT 128
#define KT 64

struct FlashSmemH {
    __half Q[QT][72];
    __half K[2][KT][72];
    __half Vt[2][HD][72];    // [d][kv]
    __half P[QT][72];
};

__global__ void __launch_bounds__(256)
flash_attn_kernel(const __half* __restrict__ qkv16, const __half* __restrict__ vt,
                  __half* __restrict__ ctx16)
{
    extern __shared__ char smraw[];
    FlashSmemH& sm = *reinterpret_cast<FlashSmemH*>(smraw);
    const int tid  = threadIdx.x;
    const int lane = tid & 31, w = tid >> 5;
    const int g = lane >> 2, t = lane & 3;
    const int mB = w * 16;

    const int q0  = blockIdx.x * QT;
    const int bh  = blockIdx.y;
    const int b   = bh / NHEAD, h = bh - b * NHEAD;
    const int dir = blockIdx.z;

    const __half* qb = qkv16 + ((size_t)(dir * BATCH + b) * SEQ) * QKVC + h * HD;
    const __half* kb = qkv16 + ((size_t)((1 - dir) * BATCH + b) * SEQ) * QKVC + DIM + h * HD;
    const __half* vtb = vt + (size_t)((1 - dir) * 96 + b * NHEAD + h) * HD * SEQ;

    for (int l = tid; l < QT * 8; l += 256) {
        int r = l >> 3, c = (l & 7) * 8;
        cp_async16(smem_u32(&sm.Q[r][c]), qb + (size_t)(q0 + r) * QKVC + c);
    }
    for (int l = tid; l < KT * 8; l += 256) {
        int r = l >> 3, c = (l & 7) * 8;
        cp_async16(smem_u32(&sm.K[0][r][c]),  kb  + (size_t)r * QKVC + c);
        cp_async16(smem_u32(&sm.Vt[0][r][c]), vtb + (size_t)r * SEQ + c);
    }
    cp_commit();

    float m0 = -1e30f, m1 = -1e30f, l0 = 0.f, l1 = 0.f;
    float O[8][4] = {};

    const int NIT = SEQ / KT;
    for (int it = 0; it < NIT; ++it) {
        if (it + 1 < NIT) {
            const int nb = (it + 1) & 1;
            const int kv = (it + 1) * KT;
            for (int l = tid; l < KT * 8; l += 256) {
                int r = l >> 3, c = (l & 7) * 8;
                cp_async16(smem_u32(&sm.K[nb][r][c]),  kb  + (size_t)(kv + r) * QKVC + c);
                cp_async16(smem_u32(&sm.Vt[nb][r][c]), vtb + (size_t)r * SEQ + kv + c);
            }
            cp_commit();
            cp_wait<1>();
        } else {
            cp_wait<0>();
        }
        __syncthreads();
        const int buf = it & 1;

        // ---- S = Q @ K^T : warp does 16 q-rows x 64 kv, hd=64 = 4 k16 slices
        float sf[8][4] = {};
#pragma unroll
        for (int ks = 0; ks < 4; ks++) {
            int kc = ks * 16 + 2 * t;
            uint32_t af[4];
            af[0] = ld32h(&sm.Q[mB + g    ][kc    ]);
            af[1] = ld32h(&sm.Q[mB + g + 8][kc    ]);
            af[2] = ld32h(&sm.Q[mB + g    ][kc + 8]);
            af[3] = ld32h(&sm.Q[mB + g + 8][kc + 8]);
#pragma unroll
            for (int ni = 0; ni < 8; ni++) {
                uint32_t bf[2] = { ld32h(&sm.K[buf][ni * 8 + g][kc    ]),
                                   ld32h(&sm.K[buf][ni * 8 + g][kc + 8]) };
                mma_f16(sf[ni], af, bf);
            }
        }

        // ---- online softmax ----
        float mx0 = -1e30f, mx1 = -1e30f;
#pragma unroll
        for (int ni = 0; ni < 8; ni++) {
#pragma unroll
            for (int c = 0; c < 4; c++) sf[ni][c] *= 0.125f;
            mx0 = fmaxf(mx0, fmaxf(sf[ni][0], sf[ni][1]));
            mx1 = fmaxf(mx1, fmaxf(sf[ni][2], sf[ni][3]));
        }
        mx0 = fmaxf(mx0, __shfl_xor_sync(0xffffffffu, mx0, 1));
        mx0 = fmaxf(mx0, __shfl_xor_sync(0xffffffffu, mx0, 2));
        mx1 = fmaxf(mx1, __shfl_xor_sync(0xffffffffu, mx1, 1));
        mx1 = fmaxf(mx1, __shfl_xor_sync(0xffffffffu, mx1, 2));
        const float nm0 = fmaxf(m0, mx0), nm1 = fmaxf(m1, mx1);
        const float a0 = __expf(m0 - nm0), a1 = __expf(m1 - nm1);
        m0 = nm0; m1 = nm1;

        float s0 = 0.f, s1 = 0.f;
#pragma unroll
        for (int ni = 0; ni < 8; ni++) {
            sf[ni][0] = __expf(sf[ni][0] - m0);
            sf[ni][1] = __expf(sf[ni][1] - m0);
            sf[ni][2] = __expf(sf[ni][2] - m1);
            sf[ni][3] = __expf(sf[ni][3] - m1);
            s0 += sf[ni][0] + sf[ni][1];
            s1 += sf[ni][2] + sf[ni][3];
            *(__half2*)&sm.P[mB + g    ][ni * 8 + 2 * t] = __floats2half2_rn(sf[ni][0], sf[ni][1]);
            *(__half2*)&sm.P[mB + g + 8][ni * 8 + 2 * t] = __floats2half2_rn(sf[ni][2], sf[ni][3]);
        }
        s0 += __shfl_xor_sync(0xffffffffu, s0, 1);
        s0 += __shfl_xor_sync(0xffffffffu, s0, 2);
        s1 += __shfl_xor_sync(0xffffffffu, s1, 1);
        s1 += __shfl_xor_sync(0xffffffffu, s1, 2);
        l0 = l0 * a0 + s0;
        l1 = l1 * a1 + s1;
#pragma unroll
        for (int ni = 0; ni < 8; ni++) {
            O[ni][0] *= a0; O[ni][1] *= a0;
            O[ni][2] *= a1; O[ni][3] *= a1;
        }
        __syncwarp();

        // ---- O += P @ V : kv=64 = 4 k16 slices, d=64 = 8 n-tiles ----
#pragma unroll
        for (int ks = 0; ks < 4; ks++) {
            int kc = ks * 16 + 2 * t;
            uint32_t af[4];
            af[0] = ld32h(&sm.P[mB + g    ][kc    ]);
            af[1] = ld32h(&sm.P[mB + g + 8][kc    ]);
            af[2] = ld32h(&sm.P[mB + g    ][kc + 8]);
            af[3] = ld32h(&sm.P[mB + g + 8][kc + 8]);
#pragma unroll
            for (int ni = 0; ni < 8; ni++) {
                uint32_t bf[2] = { ld32h(&sm.Vt[buf][ni * 8 + g][kc    ]),
                                   ld32h(&sm.Vt[buf][ni * 8 + g][kc + 8]) };
                mma_f16(O[ni], af, bf);
            }
        }
        __syncthreads();
    }

    const float inv0 = 1.f / l0, inv1 = 1.f / l1;
    __half* cbase = ctx16 + ((size_t)(dir * BATCH + b) * SEQ + q0 + mB) * DIM + h * HD;
#pragma unroll
    for (int ni = 0; ni < 8; ni++) {
        int c = ni * 8 + 2 * t;
        *(__half2*)&cbase[(size_t)(g    ) * DIM + c] =
            __floats2half2_rn(O[ni][0] * inv0, O[ni][1] * inv0);
        *(__half2*)&cbase[(size_t)(g + 8) * DIM + c] =
            __floats2half2_rn(O[ni][2] * inv1, O[ni][3] * inv1);
    }
}

// ---------------- LayerNorm (fp32 in, optional fp32 out + fp16 out) ---------
__global__ void ln_kernel(const float* __restrict__ x, const float* __restrict__ w,
                          const float* __restrict__ b, float* __restrict__ out32,
                          __half* __restrict__ out16) {
    int row = blockIdx.x;
    const float* xr = x + (size_t)row * DIM;
    float v[3];
    float s = 0.f, ss = 0.f;
#pragma unroll
    for (int i = 0; i < 3; i++) {
        v[i] = xr[threadIdx.x + i * 256];
        s += v[i]; ss += v[i] * v[i];
    }
    __shared__ float red0[8], red1[8];
    int lane = threadIdx.x & 31, wp = threadIdx.x >> 5;
#pragma unroll
    for (int o = 16; o; o >>= 1) {
        s  += __shfl_xor_sync(0xffffffffu, s, o);
        ss += __shfl_xor_sync(0xffffffffu, ss, o);
    }
    if (lane == 0) { red0[wp] = s; red1[wp] = ss; }
    __syncthreads();
    s = 0.f; ss = 0.f;
#pragma unroll
    for (int i = 0; i < 8; i++) { s += red0[i]; ss += red1[i]; }
    float mean = s * (1.f / DIM);
    float var  = ss * (1.f / DIM) - mean * mean;
    float inv  = rsqrtf(var + EPSI);
#pragma unroll
    for (int i = 0; i < 3; i++) {
        int c = threadIdx.x + i * 256;
        float y = (v[i] - mean) * inv * w[c] + b[c];
        if (out32) out32[(size_t)row * DIM + c] = y;
        out16[(size_t)row * DIM + c] = __float2half(y);
    }
}

// ---------------- per-head LN: fp32 in-place + fp16 copy --------------------
__global__ void head_ln_kernel(float* __restrict__ qkv, __half* __restrict__ qkv16,
                               const float* __restrict__ w, const float* __restrict__ b,
                               size_t nchunks) {
    size_t warp = ((size_t)blockIdx.x * blockDim.x + threadIdx.x) >> 5;
    int lane = threadIdx.x & 31;
    if (warp >= nchunks) return;
    float* ptr = qkv + warp * 64;
    __half* p16 = qkv16 + warp * 64;
    float x0 = ptr[lane], x1 = ptr[lane + 32];
    float s = x0 + x1, ss = x0 * x0 + x1 * x1;
#pragma unroll
    for (int o = 16; o; o >>= 1) {
        s  += __shfl_xor_sync(0xffffffffu, s, o);
        ss += __shfl_xor_sync(0xffffffffu, ss, o);
    }
    float mean = s * (1.f / 64.f);
    float var  = ss * (1.f / 64.f) - mean * mean;
    float inv  = rsqrtf(var + EPSI);
    float y0 = (x0 - mean) * inv * w[lane]      + b[lane];
    float y1 = (x1 - mean) * inv * w[lane + 32] + b[lane + 32];
    ptr[lane]       = y0;
    ptr[lane + 32]  = y1;
    p16[lane]       = __float2half(y0);
    p16[lane + 32]  = __float2half(y1);
}

// ------- residual: res[dir] = xn[dir] + p[other] + remap(q[other]) ----------
__global__ void residual_kernel(const float* __restrict__ xn, const float* __restrict__ p,
                                const float* __restrict__ qkv, float* __restrict__ res)
{
    const size_t BNC = (size_t)BATCH * SEQ * DIM;
    size_t idx = (size_t)blockIdx.x * 256 + threadIdx.x;
    if (idx >= 2 * BNC) return;
    int dir = (int)(idx / BNC);
    size_t rem = idx - (size_t)dir * BNC;
    int b = (int)(rem / (SEQ * DIM));
    int t = (int)(rem % (SEQ * DIM));
    int other = 1 - dir;
    int h  = t >> 16;
    int r2 = t & 65535;
    int n2 = r2 >> 6;
    int d  = r2 & 63;
    float qv = qkv[((size_t)(other * BATCH + b) * SEQ + n2) * QKVC + h * HD + d];
    res[idx] = xn[idx] + p[(size_t)other * BNC + rem] + qv;
}

// ---------------------------------------------------------------------------
extern "C" void kernel_launch(void* const* d_in, const int* in_sizes, int n_in,
                              void* d_out, int out_size) {
    const float* before  = (const float*)d_in[0];
    const float* after   = (const float*)d_in[1];
    const float* norm1_w = (const float*)d_in[2];
    const float* norm1_b = (const float*)d_in[3];
    const float* qkv_w   = (const float*)d_in[4];
    const float* hln_w   = (const float*)d_in[5];
    const float* hln_b   = (const float*)d_in[6];
    const float* proj_w  = (const float*)d_in[7];
    const float* proj_b  = (const float*)d_in[8];
    const float* norm2_w = (const float*)d_in[9];
    const float* norm2_b = (const float*)d_in[10];
    const float* fc1_w   = (const float*)d_in[11];
    const float* fc1_b   = (const float*)d_in[12];
    const float* fc2_w   = (const float*)d_in[13];
    const float* fc2_b   = (const float*)d_in[14];
    float* out = (float*)d_out;

    float  *xn, *qkv, *p, *res;
    __half *xn16, *qkv16, *vt, *ctx16, *ln216, *h16, *w16;
    cudaGetSymbolAddress((void**)&xn,    g_xn);
    cudaGetSymbolAddress((void**)&qkv,   g_qkv);
    cudaGetSymbolAddress((void**)&p,     g_p);
    cudaGetSymbolAddress((void**)&res,   g_res);
    cudaGetSymbolAddress((void**)&xn16,  g_xn16);
    cudaGetSymbolAddress((void**)&qkv16, g_qkv16);
    cudaGetSymbolAddress((void**)&vt,    g_vt);
    cudaGetSymbolAddress((void**)&ctx16, g_ctx16);
    cudaGetSymbolAddress((void**)&ln216, g_ln216);
    cudaGetSymbolAddress((void**)&h16,   g_h16);
    cudaGetSymbolAddress((void**)&w16,   g_w16);

    const size_t BNC = (size_t)BATCH * SEQ * DIM;
    const int ROWS1 = BATCH * SEQ;          // 8192
    const int ROWS2 = 2 * ROWS1;            // 16384

    cudaFuncSetAttribute(flash_attn_kernel, cudaFuncAttributeMaxDynamicSharedMemorySize,
                         (int)sizeof(FlashSmemH));

    // 0. weight conversion (fp32 -> fp16)
    f2h_kernel<<<(QKVC * DIM / 4 + 255) / 256, 256>>>(qkv_w,  w16 + W16_QKV,  QKVC * DIM);
    f2h_kernel<<<(DIM * DIM / 4 + 255) / 256, 256>>>(proj_w, w16 + W16_PROJ, DIM * DIM);
    f2h_kernel<<<(HIDDEN * DIM / 4 + 255) / 256, 256>>>(fc1_w, w16 + W16_FC1, HIDDEN * DIM);
    f2h_kernel<<<(DIM * HIDDEN / 4 + 255) / 256, 256>>>(fc2_w, w16 + W16_FC2, DIM * HIDDEN);

    // 1. norm1 on both streams (fp32 + fp16 outputs)
    ln_kernel<<<ROWS1, 256>>>(before, norm1_w, norm1_b, xn,       xn16);
    ln_kernel<<<ROWS1, 256>>>(after,  norm1_w, norm1_b, xn + BNC, xn16 + BNC);

    // 2. fused-stream QKV GEMM (fp16 mma) -> fp32 qkv
    hgemm<0,false,false><<<dim3(QKVC/BN, ROWS2/BM), 256>>>(
        xn16, w16 + W16_QKV, nullptr, nullptr, qkv, DIM, QKVC);

    // 3. per-head LN (fp32 in-place + fp16 copy)
    {
        size_t nchunks = (size_t)ROWS2 * QKVC / 64;
        int blocks = (int)((nchunks * 32 + 255) / 256);
        head_ln_kernel<<<blocks, 256>>>(qkv, qkv16, hln_w, hln_b, nchunks);
    }

    // 3b. V transpose -> fp16 Vt
    vt_kernel<<<dim3(SEQ/64, 2*BATCH*NHEAD), 256>>>(qkv, vt);

    // 4. fused fp16 flash cross-attention
    flash_attn_kernel<<<dim3(SEQ/QT, BATCH*NHEAD, 2), 256, sizeof(FlashSmemH)>>>(
        qkv16, vt, ctx16);

    // 5. output projection -> fp32 p
    hgemm<0,false,false><<<dim3(DIM/BN, ROWS2/BM), 256>>>(
        ctx16, w16 + W16_PROJ, proj_b, nullptr, p, DIM, DIM);

    // 6. attention residual with cross-stream swap + faithful q-remap (fp32)
    residual_kernel<<<(int)((2 * BNC + 255) / 256), 256>>>(xn, p, qkv, res);

    // 7. norm2 -> fp16 only
    ln_kernel<<<ROWS2, 256>>>(res, norm2_w, norm2_b, nullptr, ln216);

    // 8. MLP: fc1 + exact GELU -> fp16 h
    hgemm<1,true,false><<<dim3(HIDDEN/BN, ROWS2/BM), 256>>>(
        ln216, w16 + W16_FC1, fc1_b, nullptr, h16, DIM, HIDDEN);

    // 9. fc2 + bias + residual -> fp32 out
    hgemm<0,false,true><<<dim3(DIM/BN, ROWS2/BM), 256>>>(
        h16, w16 + W16_FC2, fc2_b, res, out, HIDDEN, DIM);
}

// round 8
// speedup vs baseline: 5.8137x; 1.0001x over previous
#include <cuda_runtime.h>
#include <cuda_fp16.h>
#include <math.h>
#include <stdint.h>

#define BATCH 8
#define SEQ 1024
#define DIM 768
#define NHEAD 12
#define HD 64
#define QKVC 2304
#define HIDDEN 3072
#define EPSI 1e-5f

// ---------------- scratch (device globals: allocation-free contract) --------
__device__ float  g_xn  [2ull*BATCH*SEQ*DIM];
__device__ float  g_qkv [2ull*BATCH*SEQ*QKVC];
__device__ float  g_p   [2ull*BATCH*SEQ*DIM];
__device__ float  g_res [2ull*BATCH*SEQ*DIM];
__device__ __half g_xn16 [2ull*BATCH*SEQ*DIM];
__device__ __half g_qkv16[2ull*BATCH*SEQ*QKVC];
__device__ __half g_vt   [2ull*BATCH*NHEAD*HD*SEQ];   // V transposed: [dir][b][h][d][kv]
__device__ __half g_ctx16[2ull*BATCH*SEQ*DIM];
__device__ __half g_ln216[2ull*BATCH*SEQ*DIM];
__device__ __half g_h16  [2ull*BATCH*SEQ*HIDDEN];
__device__ __half g_w16  [7077888];                   // qkv_w|proj_w|fc1_w|fc2_w

#define W16_QKV  0
#define W16_PROJ 1769472
#define W16_FC1  2359296
#define W16_FC2  4718592

// ---------------- async copy helpers ---------------------------------------
__device__ __forceinline__ void cp_async16(uint32_t smem, const void* g) {
    asm volatile("cp.async.cg.shared.global [%0], [%1], 16;" :: "r"(smem), "l"(g));
}
__device__ __forceinline__ void cp_commit() {
    asm volatile("cp.async.commit_group;");
}
template<int N> __device__ __forceinline__ void cp_wait() {
    asm volatile("cp.async.wait_group %0;" :: "n"(N));
}
__device__ __forceinline__ uint32_t smem_u32(const void* p) {
    return (uint32_t)__cvta_generic_to_shared(p);
}
__device__ __forceinline__ uint32_t ld32h(const __half* p) {   // aligned 32-bit load
    return *(const uint32_t*)p;
}

// ---------------- m16n8k16 fp16 mma (fp32 accum) ----------------------------
__device__ __forceinline__ void mma_f16(float* c, const uint32_t* a, const uint32_t* b) {
    asm volatile(
        "mma.sync.aligned.m16n8k16.row.col.f32.f16.f16.f32 "
        "{%0,%1,%2,%3}, {%4,%5,%6,%7}, {%8,%9}, {%0,%1,%2,%3};"
        : "+f"(c[0]), "+f"(c[1]), "+f"(c[2]), "+f"(c[3])
        : "r"(a[0]), "r"(a[1]), "r"(a[2]), "r"(a[3]), "r"(b[0]), "r"(b[1]));
}

// ---------------- fp32 -> fp16 elementwise convert --------------------------
__global__ void f2h_kernel(const float* __restrict__ x, __half* __restrict__ y, int n) {
    int i = (blockIdx.x * 256 + threadIdx.x) * 4;
    if (i >= n) return;
    float4 v = *(const float4*)&x[i];
    *(__half2*)&y[i]     = __floats2half2_rn(v.x, v.y);
    *(__half2*)&y[i + 2] = __floats2half2_rn(v.z, v.w);
}

// ================= dense fp16 tensor-core GEMM ==============================
// C = act(A @ W^T + bias) [+ resid].  A:(M,K) fp16, W:(N,K) fp16.
#define BM 128
#define BN 128
#define BK 32
#define SA 40   // smem row stride in halves (80B: 16B-aligned, conflict-free map)

template<int ACT, bool OUT_HALF, bool HAS_RES>
__global__ void __launch_bounds__(256)
hgemm(const __half* __restrict__ A, const __half* __restrict__ W,
      const float* __restrict__ bias, const float* __restrict__ resid,
      void* __restrict__ Cv, int K, int N)
{
    __shared__ __half As[2][BM][SA];
    __shared__ __half Bs[2][BN][SA];

    const int tid = threadIdx.x;
    const int lane = tid & 31, wid = tid >> 5;
    const int g = lane >> 2, t = lane & 3;
    const int wr = wid & 1, wc = wid >> 1;          // 2x4 warp grid: 64x32 tiles
    const int mB = wr * 64, nB = wc * 32;
    const int m0 = blockIdx.y * BM, n0 = blockIdx.x * BN;

    auto load_stage = [&](int buf, int k0) {
        const __half* aSrc = A + (size_t)m0 * K + k0;
#pragma unroll
        for (int i = 0; i < 2; i++) {                // 128 rows x 4 chunks / 256 thr
            int l = tid + i * 256;
            int r = l >> 2, q = l & 3;
            cp_async16(smem_u32(&As[buf][r][q * 8]), aSrc + (size_t)r * K + q * 8);
        }
        const __half* bSrc = W + (size_t)n0 * K + k0;
#pragma unroll
        for (int i = 0; i < 2; i++) {
            int l = tid + i * 256;
            int r = l >> 2, q = l & 3;
            cp_async16(smem_u32(&Bs[buf][r][q * 8]), bSrc + (size_t)r * K + q * 8);
        }
        cp_commit();
    };

    float acc[4][4][4];
#pragma unroll
    for (int mi = 0; mi < 4; mi++)
#pragma unroll
        for (int ni = 0; ni < 4; ni++)
#pragma unroll
            for (int r = 0; r < 4; r++) acc[mi][ni][r] = 0.f;

    const int nIter = K / BK;
    load_stage(0, 0);

    for (int it = 0; it < nIter; ++it) {
        if (it + 1 < nIter) {
            load_stage((it + 1) & 1, (it + 1) * BK);
            cp_wait<1>();
        } else {
            cp_wait<0>();
        }
        __syncthreads();
        const int buf = it & 1;
#pragma unroll
        for (int ks = 0; ks < 2; ks++) {             // two k16 slices in BK=32
            uint32_t af[4][4];
#pragma unroll
            for (int mi = 0; mi < 4; mi++) {
                int mr = mB + mi * 16 + g;
                int kc = ks * 16 + 2 * t;
                af[mi][0] = ld32h(&As[buf][mr    ][kc    ]);
                af[mi][1] = ld32h(&As[buf][mr + 8][kc    ]);
                af[mi][2] = ld32h(&As[buf][mr    ][kc + 8]);
                af[mi][3] = ld32h(&As[buf][mr + 8][kc + 8]);
            }
            uint32_t bf[4][2];
#pragma unroll
            for (int ni = 0; ni < 4; ni++) {
                int nc = nB + ni * 8 + g;
                int kc = ks * 16 + 2 * t;
                bf[ni][0] = ld32h(&Bs[buf][nc][kc    ]);
                bf[ni][1] = ld32h(&Bs[buf][nc][kc + 8]);
            }
#pragma unroll
            for (int mi = 0; mi < 4; mi++)
#pragma unroll
                for (int ni = 0; ni < 4; ni++)
                    mma_f16(acc[mi][ni], af[mi], bf[ni]);
        }
        __syncthreads();
    }

    // epilogue
#pragma unroll
    for (int mi = 0; mi < 4; mi++) {
        int r0 = m0 + mB + mi * 16 + g;
        int r1 = r0 + 8;
#pragma unroll
        for (int ni = 0; ni < 4; ni++) {
            int c = n0 + nB + ni * 8 + 2 * t;
            float v[4] = { acc[mi][ni][0], acc[mi][ni][1], acc[mi][ni][2], acc[mi][ni][3] };
            if (bias) {
                float b0 = bias[c], b1 = bias[c + 1];
                v[0] += b0; v[1] += b1; v[2] += b0; v[3] += b1;
            }
            if (ACT == 1) {
#pragma unroll
                for (int r = 0; r < 4; r++)
                    v[r] = 0.5f * v[r] * (1.f + erff(v[r] * 0.70710678118654752f));
            }
            if (HAS_RES) {
                v[0] += resid[(size_t)r0 * N + c];
                v[1] += resid[(size_t)r0 * N + c + 1];
                v[2] += resid[(size_t)r1 * N + c];
                v[3] += resid[(size_t)r1 * N + c + 1];
            }
            if (OUT_HALF) {
                __half* Ch = (__half*)Cv;
                *(__half2*)&Ch[(size_t)r0 * N + c] = __floats2half2_rn(v[0], v[1]);
                *(__half2*)&Ch[(size_t)r1 * N + c] = __floats2half2_rn(v[2], v[3]);
            } else {
                float* Cf = (float*)Cv;
                *(float2*)&Cf[(size_t)r0 * N + c] = make_float2(v[0], v[1]);
                *(float2*)&Cf[(size_t)r1 * N + c] = make_float2(v[2], v[3]);
            }
        }
    }
}

// ================= V transpose: qkv fp32 -> Vt fp16 [dbh][d][kv] ============
__global__ void vt_kernel(const float* __restrict__ qkv, __half* __restrict__ vt)
{
    __shared__ __half s[64][72];
    const int dbh = blockIdx.y;               // dir*96 + b*12 + h
    const int kv0 = blockIdx.x * 64;
    const int dir = dbh / 96, rem = dbh % 96;
    const int b = rem / NHEAD, h = rem % NHEAD;
    const int tid = threadIdx.x;
    const float* src = qkv + ((size_t)(dir * BATCH + b) * SEQ) * QKVC + 2 * DIM + h * HD;
    for (int l = tid; l < 64 * 64; l += 256) {
        int r = l >> 6, c = l & 63;           // r = kv-local, c = d (coalesced read)
        s[c][r] = __float2half(src[(size_t)(kv0 + r) * QKVC + c]);
    }
    __syncthreads();
    __half* dst = vt + (size_t)dbh * HD * SEQ + kv0;
    for (int l = tid; l < 64 * 64; l += 256) {
        int d = l >> 6, kk = l & 63;          // coalesced write
        dst[(size_t)d * SEQ + kk] = s[d][kk];
    }
}

// ================= fused fp16 flash cross-attention =========================
#define QT 128
#define KT 64

struct FlashSmemH {
    __half Q[QT][72];
    __half K[2][KT][72];
    __half Vt[2][HD][72];    // [d][kv]
    __half P[QT][72];
};

__global__ void __launch_bounds__(256)
flash_attn_kernel(const __half* __restrict__ qkv16, const __half* __restrict__ vt,
                  __half* __restrict__ ctx16)
{
    extern __shared__ char smraw[];
    FlashSmemH& sm = *reinterpret_cast<FlashSmemH*>(smraw);
    const int tid  = threadIdx.x;
    const int lane = tid & 31, w = tid >> 5;
    const int g = lane >> 2, t = lane & 3;
    const int mB = w * 16;

    const int q0  = blockIdx.x * QT;
    const int bh  = blockIdx.y;
    const int b   = bh / NHEAD, h = bh - b * NHEAD;
    const int dir = blockIdx.z;

    const __half* qb = qkv16 + ((size_t)(dir * BATCH + b) * SEQ) * QKVC + h * HD;
    const __half* kb = qkv16 + ((size_t)((1 - dir) * BATCH + b) * SEQ) * QKVC + DIM + h * HD;
    const __half* vtb = vt + (size_t)((1 - dir) * 96 + b * NHEAD + h) * HD * SEQ;

    for (int l = tid; l < QT * 8; l += 256) {
        int r = l >> 3, c = (l & 7) * 8;
        cp_async16(smem_u32(&sm.Q[r][c]), qb + (size_t)(q0 + r) * QKVC + c);
    }
    for (int l = tid; l < KT * 8; l += 256) {
        int r = l >> 3, c = (l & 7) * 8;
        cp_async16(smem_u32(&sm.K[0][r][c]),  kb  + (size_t)r * QKVC + c);
        cp_async16(smem_u32(&sm.Vt[0][r][c]), vtb + (size_t)r * SEQ + c);
    }
    cp_commit();

    float m0 = -1e30f, m1 = -1e30f, l0 = 0.f, l1 = 0.f;
    float O[8][4] = {};

    const int NIT = SEQ / KT;
    for (int it = 0; it < NIT; ++it) {
        if (it + 1 < NIT) {
            const int nb = (it + 1) & 1;
            const int kv = (it + 1) * KT;
            for (int l = tid; l < KT * 8; l += 256) {
                int r = l >> 3, c = (l & 7) * 8;
                cp_async16(smem_u32(&sm.K[nb][r][c]),  kb  + (size_t)(kv + r) * QKVC + c);
                cp_async16(smem_u32(&sm.Vt[nb][r][c]), vtb + (size_t)r * SEQ + kv + c);
            }
            cp_commit();
            cp_wait<1>();
        } else {
            cp_wait<0>();
        }
        __syncthreads();
        const int buf = it & 1;

        // ---- S = Q @ K^T : warp does 16 q-rows x 64 kv, hd=64 = 4 k16 slices
        float sf[8][4] = {};
#pragma unroll
        for (int ks = 0; ks < 4; ks++) {
            int kc = ks * 16 + 2 * t;
            uint32_t af[4];
            af[0] = ld32h(&sm.Q[mB + g    ][kc    ]);
            af[1] = ld32h(&sm.Q[mB + g + 8][kc    ]);
            af[2] = ld32h(&sm.Q[mB + g    ][kc + 8]);
            af[3] = ld32h(&sm.Q[mB + g + 8][kc + 8]);
#pragma unroll
            for (int ni = 0; ni < 8; ni++) {
                uint32_t bf[2] = { ld32h(&sm.K[buf][ni * 8 + g][kc    ]),
                                   ld32h(&sm.K[buf][ni * 8 + g][kc + 8]) };
                mma_f16(sf[ni], af, bf);
            }
        }

        // ---- online softmax ----
        float mx0 = -1e30f, mx1 = -1e30f;
#pragma unroll
        for (int ni = 0; ni < 8; ni++) {
#pragma unroll
            for (int c = 0; c < 4; c++) sf[ni][c] *= 0.125f;
            mx0 = fmaxf(mx0, fmaxf(sf[ni][0], sf[ni][1]));
            mx1 = fmaxf(mx1, fmaxf(sf[ni][2], sf[ni][3]));
        }
        mx0 = fmaxf(mx0, __shfl_xor_sync(0xffffffffu, mx0, 1));
        mx0 = fmaxf(mx0, __shfl_xor_sync(0xffffffffu, mx0, 2));
        mx1 = fmaxf(mx1, __shfl_xor_sync(0xffffffffu, mx1, 1));
        mx1 = fmaxf(mx1, __shfl_xor_sync(0xffffffffu, mx1, 2));
        const float nm0 = fmaxf(m0, mx0), nm1 = fmaxf(m1, mx1);
        const float a0 = __expf(m0 - nm0), a1 = __expf(m1 - nm1);
        m0 = nm0; m1 = nm1;

        float s0 = 0.f, s1 = 0.f;
#pragma unroll
        for (int ni = 0; ni < 8; ni++) {
            sf[ni][0] = __expf(sf[ni][0] - m0);
            sf[ni][1] = __expf(sf[ni][1] - m0);
            sf[ni][2] = __expf(sf[ni][2] - m1);
            sf[ni][3] = __expf(sf[ni][3] - m1);
            s0 += sf[ni][0] + sf[ni][1];
            s1 += sf[ni][2] + sf[ni][3];
            *(__half2*)&sm.P[mB + g    ][ni * 8 + 2 * t] = __floats2half2_rn(sf[ni][0], sf[ni][1]);
            *(__half2*)&sm.P[mB + g + 8][ni * 8 + 2 * t] = __floats2half2_rn(sf[ni][2], sf[ni][3]);
        }
        s0 += __shfl_xor_sync(0xffffffffu, s0, 1);
        s0 += __shfl_xor_sync(0xffffffffu, s0, 2);
        s1 += __shfl_xor_sync(0xffffffffu, s1, 1);
        s1 += __shfl_xor_sync(0xffffffffu, s1, 2);
        l0 = l0 * a0 + s0;
        l1 = l1 * a1 + s1;
#pragma unroll
        for (int ni = 0; ni < 8; ni++) {
            O[ni][0] *= a0; O[ni][1] *= a0;
            O[ni][2] *= a1; O[ni][3] *= a1;
        }
        __syncwarp();

        // ---- O += P @ V : kv=64 = 4 k16 slices, d=64 = 8 n-tiles ----
#pragma unroll
        for (int ks = 0; ks < 4; ks++) {
            int kc = ks * 16 + 2 * t;
            uint32_t af[4];
            af[0] = ld32h(&sm.P[mB + g    ][kc    ]);
            af[1] = ld32h(&sm.P[mB + g + 8][kc    ]);
            af[2] = ld32h(&sm.P[mB + g    ][kc + 8]);
            af[3] = ld32h(&sm.P[mB + g + 8][kc + 8]);
#pragma unroll
            for (int ni = 0; ni < 8; ni++) {
                uint32_t bf[2] = { ld32h(&sm.Vt[buf][ni * 8 + g][kc    ]),
                                   ld32h(&sm.Vt[buf][ni * 8 + g][kc + 8]) };
                mma_f16(O[ni], af, bf);
            }
        }
        __syncthreads();
    }

    const float inv0 = 1.f / l0, inv1 = 1.f / l1;
    __half* cbase = ctx16 + ((size_t)(dir * BATCH + b) * SEQ + q0 + mB) * DIM + h * HD;
#pragma unroll
    for (int ni = 0; ni < 8; ni++) {
        int c = ni * 8 + 2 * t;
        *(__half2*)&cbase[(size_t)(g    ) * DIM + c] =
            __floats2half2_rn(O[ni][0] * inv0, O[ni][1] * inv0);
        *(__half2*)&cbase[(size_t)(g + 8) * DIM + c] =
            __floats2half2_rn(O[ni][2] * inv1, O[ni][3] * inv1);
    }
}

// ---------------- LayerNorm (fp32 in, optional fp32 out + fp16 out) ---------
__global__ void ln_kernel(const float* __restrict__ x, const float* __restrict__ w,
                          const float* __restrict__ b, float* __restrict__ out32,
                          __half* __restrict__ out16) {
    int row = blockIdx.x;
    const float* xr = x + (size_t)row * DIM;
    float v[3];
    float s = 0.f, ss = 0.f;
#pragma unroll
    for (int i = 0; i < 3; i++) {
        v[i] = xr[threadIdx.x + i * 256];
        s += v[i]; ss += v[i] * v[i];
    }
    __shared__ float red0[8], red1[8];
    int lane = threadIdx.x & 31, wp = threadIdx.x >> 5;
#pragma unroll
    for (int o = 16; o; o >>= 1) {
        s  += __shfl_xor_sync(0xffffffffu, s, o);
        ss += __shfl_xor_sync(0xffffffffu, ss, o);
    }
    if (lane == 0) { red0[wp] = s; red1[wp] = ss; }
    __syncthreads();
    s = 0.f; ss = 0.f;
#pragma unroll
    for (int i = 0; i < 8; i++) { s += red0[i]; ss += red1[i]; }
    float mean = s * (1.f / DIM);
    float var  = ss * (1.f / DIM) - mean * mean;
    float inv  = rsqrtf(var + EPSI);
#pragma unroll
    for (int i = 0; i < 3; i++) {
        int c = threadIdx.x + i * 256;
        float y = (v[i] - mean) * inv * w[c] + b[c];
        if (out32) out32[(size_t)row * DIM + c] = y;
        out16[(size_t)row * DIM + c] = __float2half(y);
    }
}

// ---------------- per-head LN: fp32 in-place + fp16 copy --------------------
__global__ void head_ln_kernel(float* __restrict__ qkv, __half* __restrict__ qkv16,
                               const float* __restrict__ w, const float* __restrict__ b,
                               size_t nchunks) {
    size_t warp = ((size_t)blockIdx.x * blockDim.x + threadIdx.x) >> 5;
    int lane = threadIdx.x & 31;
    if (warp >= nchunks) return;
    float* ptr = qkv + warp * 64;
    __half* p16 = qkv16 + warp * 64;
    float x0 = ptr[lane], x1 = ptr[lane + 32];
    float s = x0 + x1, ss = x0 * x0 + x1 * x1;
#pragma unroll
    for (int o = 16; o; o >>= 1) {
        s  += __shfl_xor_sync(0xffffffffu, s, o);
        ss += __shfl_xor_sync(0xffffffffu, ss, o);
    }
    float mean = s * (1.f / 64.f);
    float var  = ss * (1.f / 64.f) - mean * mean;
    float inv  = rsqrtf(var + EPSI);
    float y0 = (x0 - mean) * inv * w[lane]      + b[lane];
    float y1 = (x1 - mean) * inv * w[lane + 32] + b[lane + 32];
    ptr[lane]       = y0;
    ptr[lane + 32]  = y1;
    p16[lane]       = __float2half(y0);
    p16[lane + 32]  = __float2half(y1);
}

// ------- residual: res[dir] = xn[dir] + p[other] + remap(q[other]) ----------
__global__ void residual_kernel(const float* __restrict__ xn, const float* __restrict__ p,
                                const float* __restrict__ qkv, float* __restrict__ res)
{
    const size_t BNC = (size_t)BATCH * SEQ * DIM;
    size_t idx = (size_t)blockIdx.x * 256 + threadIdx.x;
    if (idx >= 2 * BNC) return;
    int dir = (int)(idx / BNC);
    size_t rem = idx - (size_t)dir * BNC;
    int b = (int)(rem / (SEQ * DIM));
    int t = (int)(rem % (SEQ * DIM));
    int other = 1 - dir;
    int h  = t >> 16;
    int r2 = t & 65535;
    int n2 = r2 >> 6;
    int d  = r2 & 63;
    float qv = qkv[((size_t)(other * BATCH + b) * SEQ + n2) * QKVC + h * HD + d];
    res[idx] = xn[idx] + p[(size_t)other * BNC + rem] + qv;
}

// ---------------------------------------------------------------------------
extern "C" void kernel_launch(void* const* d_in, const int* in_sizes, int n_in,
                              void* d_out, int out_size) {
    const float* before  = (const float*)d_in[0];
    const float* after   = (const float*)d_in[1];
    const float* norm1_w = (const float*)d_in[2];
    const float* norm1_b = (const float*)d_in[3];
    const float* qkv_w   = (const float*)d_in[4];
    const float* hln_w   = (const float*)d_in[5];
    const float* hln_b   = (const float*)d_in[6];
    const float* proj_w  = (const float*)d_in[7];
    const float* proj_b  = (const float*)d_in[8];
    const float* norm2_w = (const float*)d_in[9];
    const float* norm2_b = (const float*)d_in[10];
    const float* fc1_w   = (const float*)d_in[11];
    const float* fc1_b   = (const float*)d_in[12];
    const float* fc2_w   = (const float*)d_in[13];
    const float* fc2_b   = (const float*)d_in[14];
    float* out = (float*)d_out;

    float  *xn, *qkv, *p, *res;
    __half *xn16, *qkv16, *vt, *ctx16, *ln216, *h16, *w16;
    cudaGetSymbolAddress((void**)&xn,    g_xn);
    cudaGetSymbolAddress((void**)&qkv,   g_qkv);
    cudaGetSymbolAddress((void**)&p,     g_p);
    cudaGetSymbolAddress((void**)&res,   g_res);
    cudaGetSymbolAddress((void**)&xn16,  g_xn16);
    cudaGetSymbolAddress((void**)&qkv16, g_qkv16);
    cudaGetSymbolAddress((void**)&vt,    g_vt);
    cudaGetSymbolAddress((void**)&ctx16, g_ctx16);
    cudaGetSymbolAddress((void**)&ln216, g_ln216);
    cudaGetSymbolAddress((void**)&h16,   g_h16);
    cudaGetSymbolAddress((void**)&w16,   g_w16);

    const size_t BNC = (size_t)BATCH * SEQ * DIM;
    const int ROWS1 = BATCH * SEQ;          // 8192
    const int ROWS2 = 2 * ROWS1;            // 16384

    cudaFuncSetAttribute(flash_attn_kernel, cudaFuncAttributeMaxDynamicSharedMemorySize,
                         (int)sizeof(FlashSmemH));

    // 0. weight conversion (fp32 -> fp16)
    f2h_kernel<<<(QKVC * DIM / 4 + 255) / 256, 256>>>(qkv_w,  w16 + W16_QKV,  QKVC * DIM);
    f2h_kernel<<<(DIM * DIM / 4 + 255) / 256, 256>>>(proj_w, w16 + W16_PROJ, DIM * DIM);
    f2h_kernel<<<(HIDDEN * DIM / 4 + 255) / 256, 256>>>(fc1_w, w16 + W16_FC1, HIDDEN * DIM);
    f2h_kernel<<<(DIM * HIDDEN / 4 + 255) / 256, 256>>>(fc2_w, w16 + W16_FC2, DIM * HIDDEN);

    // 1. norm1 on both streams (fp32 + fp16 outputs)
    ln_kernel<<<ROWS1, 256>>>(before, norm1_w, norm1_b, xn,       xn16);
    ln_kernel<<<ROWS1, 256>>>(after,  norm1_w, norm1_b, xn + BNC, xn16 + BNC);

    // 2. fused-stream QKV GEMM (fp16 mma) -> fp32 qkv
    hgemm<0,false,false><<<dim3(QKVC/BN, ROWS2/BM), 256>>>(
        xn16, w16 + W16_QKV, nullptr, nullptr, qkv, DIM, QKVC);

    // 3. per-head LN (fp32 in-place + fp16 copy)
    {
        size_t nchunks = (size_t)ROWS2 * QKVC / 64;
        int blocks = (int)((nchunks * 32 + 255) / 256);
        head_ln_kernel<<<blocks, 256>>>(qkv, qkv16, hln_w, hln_b, nchunks);
    }

    // 3b. V transpose -> fp16 Vt
    vt_kernel<<<dim3(SEQ/64, 2*BATCH*NHEAD), 256>>>(qkv, vt);

    // 4. fused fp16 flash cross-attention
    flash_attn_kernel<<<dim3(SEQ/QT, BATCH*NHEAD, 2), 256, sizeof(FlashSmemH)>>>(
        qkv16, vt, ctx16);

    // 5. output projection -> fp32 p
    hgemm<0,false,false><<<dim3(DIM/BN, ROWS2/BM), 256>>>(
        ctx16, w16 + W16_PROJ, proj_b, nullptr, p, DIM, DIM);

    // 6. attention residual with cross-stream swap + faithful q-remap (fp32)
    residual_kernel<<<(int)((2 * BNC + 255) / 256), 256>>>(xn, p, qkv, res);

    // 7. norm2 -> fp16 only
    ln_kernel<<<ROWS2, 256>>>(res, norm2_w, norm2_b, nullptr, ln216);

    // 8. MLP: fc1 + exact GELU -> fp16 h
    hgemm<1,true,false><<<dim3(HIDDEN/BN, ROWS2/BM), 256>>>(
        ln216, w16 + W16_FC1, fc1_b, nullptr, h16, DIM, HIDDEN);

    // 9. fc2 + bias + residual -> fp32 out
    hgemm<0,false,true><<<dim3(DIM/BN, ROWS2/BM), 256>>>(
        h16, w16 + W16_FC2, fc2_b, res, out, HIDDEN, DIM);
}

// round 10
// speedup vs baseline: 6.0301x; 1.0372x over previous
#include <cuda_runtime.h>
#include <cuda_fp16.h>
#include <math.h>
#include <stdint.h>

#define BATCH 8
#define SEQ 1024
#define DIM 768
#define NHEAD 12
#define HD 64
#define QKVC 2304
#define HIDDEN 3072
#define EPSI 1e-5f

// ---------------- scratch (device globals: allocation-free contract) --------
__device__ float  g_xn  [2ull*BATCH*SEQ*DIM];
__device__ float  g_p   [2ull*BATCH*SEQ*DIM];
__device__ float  g_res [2ull*BATCH*SEQ*DIM];
__device__ __half g_xn16 [2ull*BATCH*SEQ*DIM];
__device__ __half g_qkv16[2ull*BATCH*SEQ*QKVC];
__device__ __half g_vt   [2ull*BATCH*NHEAD*HD*SEQ];   // V transposed: [dir][b][h][d][kv]
__device__ __half g_ctx16[2ull*BATCH*SEQ*DIM];
__device__ __half g_ln216[2ull*BATCH*SEQ*DIM];
__device__ __half g_h16  [2ull*BATCH*SEQ*HIDDEN];
__device__ __half g_w16  [7077888];                   // qkv_w|proj_w|fc1_w|fc2_w

#define W16_QKV  0
#define W16_PROJ 1769472
#define W16_FC1  2359296
#define W16_FC2  4718592

// ---------------- async copy helpers ---------------------------------------
__device__ __forceinline__ void cp_async16(uint32_t smem, const void* g) {
    asm volatile("cp.async.cg.shared.global [%0], [%1], 16;" :: "r"(smem), "l"(g));
}
__device__ __forceinline__ void cp_commit() {
    asm volatile("cp.async.commit_group;");
}
template<int N> __device__ __forceinline__ void cp_wait() {
    asm volatile("cp.async.wait_group %0;" :: "n"(N));
}
__device__ __forceinline__ uint32_t smem_u32(const void* p) {
    return (uint32_t)__cvta_generic_to_shared(p);
}
__device__ __forceinline__ uint32_t ld32h(const __half* p) {
    return *(const uint32_t*)p;
}
__device__ __forceinline__ void ldsm_x4(uint32_t* r, uint32_t addr) {
    asm volatile("ldmatrix.sync.aligned.m8n8.x4.shared.b16 {%0,%1,%2,%3}, [%4];"
        : "=r"(r[0]), "=r"(r[1]), "=r"(r[2]), "=r"(r[3]) : "r"(addr));
}

// ---------------- m16n8k16 fp16 mma (fp32 accum) ----------------------------
__device__ __forceinline__ void mma_f16(float* c, const uint32_t* a, const uint32_t* b) {
    asm volatile(
        "mma.sync.aligned.m16n8k16.row.col.f32.f16.f16.f32 "
        "{%0,%1,%2,%3}, {%4,%5,%6,%7}, {%8,%9}, {%0,%1,%2,%3};"
        : "+f"(c[0]), "+f"(c[1]), "+f"(c[2]), "+f"(c[3])
        : "r"(a[0]), "r"(a[1]), "r"(a[2]), "r"(a[3]), "r"(b[0]), "r"(b[1]));
}

// ---------------- fp32 -> fp16 elementwise convert --------------------------
__global__ void f2h_kernel(const float* __restrict__ x, __half* __restrict__ y, int n) {
    int i = (blockIdx.x * 256 + threadIdx.x) * 4;
    if (i >= n) return;
    float4 v = *(const float4*)&x[i];
    *(__half2*)&y[i]     = __floats2half2_rn(v.x, v.y);
    *(__half2*)&y[i + 2] = __floats2half2_rn(v.z, v.w);
}

// ================= dense fp16 tensor-core GEMM (ldmatrix, 3-stage) ==========
// C = act(A @ W^T + bias) [+ resid].  A:(M,K) fp16, W:(N,K) fp16.
#define BM 128
#define BN 128
#define BK 32
#define SA 40          // smem row stride in halves (80 B, conflict-free)
#define NSTG 3
#define STG_A (BM * SA)
#define STG_B (BN * SA)
#define HS_BYTES (NSTG * (STG_A + STG_B) * 2)

template<int ACT, bool OUT_HALF, bool HAS_RES>
__global__ void __launch_bounds__(256)
hgemm(const __half* __restrict__ A, const __half* __restrict__ W,
      const float* __restrict__ bias, const float* __restrict__ resid,
      void* __restrict__ Cv, int K, int N)
{
    extern __shared__ __half sh[];
    __half* Asm = sh;
    __half* Bsm = sh + NSTG * STG_A;

    const int tid = threadIdx.x;
    const int lane = tid & 31, wid = tid >> 5;
    const int g = lane >> 2, t = lane & 3;
    const int wr = wid & 1, wc = wid >> 1;          // 2x4 warp grid: 64x32 tiles
    const int mB = wr * 64, nB = wc * 32;
    const int m0 = blockIdx.y * BM, n0 = blockIdx.x * BN;

    // ldmatrix lane addressing (precomputed)
    const int aRow = lane & 15;
    const int aCol = (lane >> 4) * 8;
    const int bRow = ((lane >> 4) << 3) + (lane & 7);
    const int bCol = ((lane >> 3) & 1) * 8;

    auto load_stage = [&](int s, int k0) {
        const __half* aSrc = A + (size_t)m0 * K + k0;
        __half* aDst = Asm + s * STG_A;
#pragma unroll
        for (int i = 0; i < 2; i++) {                // 128 rows x 4 chunks / 256 thr
            int l = tid + i * 256;
            int r = l >> 2, q = l & 3;
            cp_async16(smem_u32(&aDst[r * SA + q * 8]), aSrc + (size_t)r * K + q * 8);
        }
        const __half* bSrc = W + (size_t)n0 * K + k0;
        __half* bDst = Bsm + s * STG_B;
#pragma unroll
        for (int i = 0; i < 2; i++) {
            int l = tid + i * 256;
            int r = l >> 2, q = l & 3;
            cp_async16(smem_u32(&bDst[r * SA + q * 8]), bSrc + (size_t)r * K + q * 8);
        }
        cp_commit();
    };

    float acc[4][4][4];
#pragma unroll
    for (int mi = 0; mi < 4; mi++)
#pragma unroll
        for (int ni = 0; ni < 4; ni++)
#pragma unroll
            for (int r = 0; r < 4; r++) acc[mi][ni][r] = 0.f;

    const int T = K / BK;
    load_stage(0, 0);
    load_stage(1, BK);

    for (int it = 0; it < T; ++it) {
        const int cur = it % NSTG;
        if (it + 2 < T) {
            load_stage((it + 2) % NSTG, (it + 2) * BK);
            cp_wait<2>();
        } else if (it + 1 < T) {
            cp_wait<1>();
        } else {
            cp_wait<0>();
        }
        __syncthreads();

        const __half* Ac = Asm + cur * STG_A;
        const __half* Bc = Bsm + cur * STG_B;
#pragma unroll
        for (int ks = 0; ks < 2; ks++) {             // two k16 slices in BK=32
            uint32_t af[4][4];
#pragma unroll
            for (int mi = 0; mi < 4; mi++)
                ldsm_x4(af[mi], smem_u32(&Ac[(mB + mi * 16 + aRow) * SA + aCol + ks * 16]));
            uint32_t bf[4][2];
#pragma unroll
            for (int nip = 0; nip < 2; nip++) {
                uint32_t r4[4];
                ldsm_x4(r4, smem_u32(&Bc[(nB + nip * 16 + bRow) * SA + bCol + ks * 16]));
                bf[2 * nip    ][0] = r4[0]; bf[2 * nip    ][1] = r4[1];
                bf[2 * nip + 1][0] = r4[2]; bf[2 * nip + 1][1] = r4[3];
            }
#pragma unroll
            for (int mi = 0; mi < 4; mi++)
#pragma unroll
                for (int ni = 0; ni < 4; ni++)
                    mma_f16(acc[mi][ni], af[mi], bf[ni]);
        }
        __syncthreads();
    }

    // epilogue
#pragma unroll
    for (int mi = 0; mi < 4; mi++) {
        int r0 = m0 + mB + mi * 16 + g;
        int r1 = r0 + 8;
#pragma unroll
        for (int ni = 0; ni < 4; ni++) {
            int c = n0 + nB + ni * 8 + 2 * t;
            float v[4] = { acc[mi][ni][0], acc[mi][ni][1], acc[mi][ni][2], acc[mi][ni][3] };
            if (bias) {
                float b0 = bias[c], b1 = bias[c + 1];
                v[0] += b0; v[1] += b1; v[2] += b0; v[3] += b1;
            }
            if (ACT == 1) {
#pragma unroll
                for (int r = 0; r < 4; r++)
                    v[r] = 0.5f * v[r] * (1.f + erff(v[r] * 0.70710678118654752f));
            }
            if (HAS_RES) {
                v[0] += resid[(size_t)r0 * N + c];
                v[1] += resid[(size_t)r0 * N + c + 1];
                v[2] += resid[(size_t)r1 * N + c];
                v[3] += resid[(size_t)r1 * N + c + 1];
            }
            if (OUT_HALF) {
                __half* Ch = (__half*)Cv;
                *(__half2*)&Ch[(size_t)r0 * N + c] = __floats2half2_rn(v[0], v[1]);
                *(__half2*)&Ch[(size_t)r1 * N + c] = __floats2half2_rn(v[2], v[3]);
            } else {
                float* Cf = (float*)Cv;
                *(float2*)&Cf[(size_t)r0 * N + c] = make_float2(v[0], v[1]);
                *(float2*)&Cf[(size_t)r1 * N + c] = make_float2(v[2], v[3]);
            }
        }
    }
}

// ================= V transpose: qkv16 -> Vt fp16 [dbh][d][kv] ===============
__global__ void vt_kernel(const __half* __restrict__ qkv16, __half* __restrict__ vt)
{
    __shared__ __half s[64][72];
    const int dbh = blockIdx.y;               // dir*96 + b*12 + h
    const int kv0 = blockIdx.x * 64;
    const int dir = dbh / 96, rem = dbh % 96;
    const int b = rem / NHEAD, h = rem % NHEAD;
    const int tid = threadIdx.x;
    const __half* src = qkv16 + ((size_t)(dir * BATCH + b) * SEQ) * QKVC + 2 * DIM + h * HD;
    for (int l = tid; l < 64 * 64; l += 256) {
        int r = l >> 6, c = l & 63;           // r = kv-local, c = d (coalesced read)
        s[c][r] = src[(size_t)(kv0 + r) * QKVC + c];
    }
    __syncthreads();
    __half* dst = vt + (size_t)dbh * HD * SEQ + kv0;
    for (int l = tid; l < 64 * 64; l += 256) {
        int d = l >> 6, kk = l & 63;          // coalesced write
        dst[(size_t)d * SEQ + kk] = s[d][kk];
    }
}

// ================= fused fp16 flash cross-attention =========================
#define QT 128
#define KT 64

struct FlashSmemH {
    __half Q[QT][72];
    __half K[2][KT][72];
    __half Vt[2][HD][72];    // [d][kv]
    __half P[QT][72];
};

__global__ void __launch_bounds__(256)
flash_attn_kernel(const __half* __restrict__ qkv16, const __half* __restrict__ vt,
                  __half* __restrict__ ctx16)
{
    extern __shared__ char smraw[];
    FlashSmemH& sm = *reinterpret_cast<FlashSmemH*>(smraw);
    const int tid  = threadIdx.x;
    const int lane = tid & 31, w = tid >> 5;
    const int g = lane >> 2, t = lane & 3;
    const int mB = w * 16;

    const int q0  = blockIdx.x * QT;
    const int bh  = blockIdx.y;
    const int b   = bh / NHEAD, h = bh - b * NHEAD;
    const int dir = blockIdx.z;

    const __half* qb = qkv16 + ((size_t)(dir * BATCH + b) * SEQ) * QKVC + h * HD;
    const __half* kb = qkv16 + ((size_t)((1 - dir) * BATCH + b) * SEQ) * QKVC + DIM + h * HD;
    const __half* vtb = vt + (size_t)((1 - dir) * 96 + b * NHEAD + h) * HD * SEQ;

    for (int l = tid; l < QT * 8; l += 256) {
        int r = l >> 3, c = (l & 7) * 8;
        cp_async16(smem_u32(&sm.Q[r][c]), qb + (size_t)(q0 + r) * QKVC + c);
    }
    for (int l = tid; l < KT * 8; l += 256) {
        int r = l >> 3, c = (l & 7) * 8;
        cp_async16(smem_u32(&sm.K[0][r][c]),  kb  + (size_t)r * QKVC + c);
        cp_async16(smem_u32(&sm.Vt[0][r][c]), vtb + (size_t)r * SEQ + c);
    }
    cp_commit();

    float m0 = -1e30f, m1 = -1e30f, l0 = 0.f, l1 = 0.f;
    float O[8][4] = {};

    const int NIT = SEQ / KT;
    for (int it = 0; it < NIT; ++it) {
        if (it + 1 < NIT) {
            const int nb = (it + 1) & 1;
            const int kv = (it + 1) * KT;
            for (int l = tid; l < KT * 8; l += 256) {
                int r = l >> 3, c = (l & 7) * 8;
                cp_async16(smem_u32(&sm.K[nb][r][c]),  kb  + (size_t)(kv + r) * QKVC + c);
                cp_async16(smem_u32(&sm.Vt[nb][r][c]), vtb + (size_t)r * SEQ + kv + c);
            }
            cp_commit();
            cp_wait<1>();
        } else {
            cp_wait<0>();
        }
        __syncthreads();
        const int buf = it & 1;

        float sf[8][4] = {};
#pragma unroll
        for (int ks = 0; ks < 4; ks++) {
            int kc = ks * 16 + 2 * t;
            uint32_t af[4];
            af[0] = ld32h(&sm.Q[mB + g    ][kc    ]);
            af[1] = ld32h(&sm.Q[mB + g + 8][kc    ]);
            af[2] = ld32h(&sm.Q[mB + g    ][kc + 8]);
            af[3] = ld32h(&sm.Q[mB + g + 8][kc + 8]);
#pragma unroll
            for (int ni = 0; ni < 8; ni++) {
                uint32_t bf[2] = { ld32h(&sm.K[buf][ni * 8 + g][kc    ]),
                                   ld32h(&sm.K[buf][ni * 8 + g][kc + 8]) };
                mma_f16(sf[ni], af, bf);
            }
        }

        float mx0 = -1e30f, mx1 = -1e30f;
#pragma unroll
        for (int ni = 0; ni < 8; ni++) {
#pragma unroll
            for (int c = 0; c < 4; c++) sf[ni][c] *= 0.125f;
            mx0 = fmaxf(mx0, fmaxf(sf[ni][0], sf[ni][1]));
            mx1 = fmaxf(mx1, fmaxf(sf[ni][2], sf[ni][3]));
        }
        mx0 = fmaxf(mx0, __shfl_xor_sync(0xffffffffu, mx0, 1));
        mx0 = fmaxf(mx0, __shfl_xor_sync(0xffffffffu, mx0, 2));
        mx1 = fmaxf(mx1, __shfl_xor_sync(0xffffffffu, mx1, 1));
        mx1 = fmaxf(mx1, __shfl_xor_sync(0xffffffffu, mx1, 2));
        const float nm0 = fmaxf(m0, mx0), nm1 = fmaxf(m1, mx1);
        const float a0 = __expf(m0 - nm0), a1 = __expf(m1 - nm1);
        m0 = nm0; m1 = nm1;

        float s0 = 0.f, s1 = 0.f;
#pragma unroll
        for (int ni = 0; ni < 8; ni++) {
            sf[ni][0] = __expf(sf[ni][0] - m0);
            sf[ni][1] = __expf(sf[ni][1] - m0);
            sf[ni][2] = __expf(sf[ni][2] - m1);
            sf[ni][3] = __expf(sf[ni][3] - m1);
            s0 += sf[ni][0] + sf[ni][1];
            s1 += sf[ni][2] + sf[ni][3];
            *(__half2*)&sm.P[mB + g    ][ni * 8 + 2 * t] = __floats2half2_rn(sf[ni][0], sf[ni][1]);
            *(__half2*)&sm.P[mB + g + 8][ni * 8 + 2 * t] = __floats2half2_rn(sf[ni][2], sf[ni][3]);
        }
        s0 += __shfl_xor_sync(0xffffffffu, s0, 1);
        s0 += __shfl_xor_sync(0xffffffffu, s0, 2);
        s1 += __shfl_xor_sync(0xffffffffu, s1, 1);
        s1 += __shfl_xor_sync(0xffffffffu, s1, 2);
        l0 = l0 * a0 + s0;
        l1 = l1 * a1 + s1;
#pragma unroll
        for (int ni = 0; ni < 8; ni++) {
            O[ni][0] *= a0; O[ni][1] *= a0;
            O[ni][2] *= a1; O[ni][3] *= a1;
        }
        __syncwarp();

#pragma unroll
        for (int ks = 0; ks < 4; ks++) {
            int kc = ks * 16 + 2 * t;
            uint32_t af[4];
            af[0] = ld32h(&sm.P[mB + g    ][kc    ]);
            af[1] = ld32h(&sm.P[mB + g + 8][kc    ]);
            af[2] = ld32h(&sm.P[mB + g    ][kc + 8]);
            af[3] = ld32h(&sm.P[mB + g + 8][kc + 8]);
#pragma unroll
            for (int ni = 0; ni < 8; ni++) {
                uint32_t bf[2] = { ld32h(&sm.Vt[buf][ni * 8 + g][kc    ]),
                                   ld32h(&sm.Vt[buf][ni * 8 + g][kc + 8]) };
                mma_f16(O[ni], af, bf);
            }
        }
        __syncthreads();
    }

    const float inv0 = 1.f / l0, inv1 = 1.f / l1;
    __half* cbase = ctx16 + ((size_t)(dir * BATCH + b) * SEQ + q0 + mB) * DIM + h * HD;
#pragma unroll
    for (int ni = 0; ni < 8; ni++) {
        int c = ni * 8 + 2 * t;
        *(__half2*)&cbase[(size_t)(g    ) * DIM + c] =
            __floats2half2_rn(O[ni][0] * inv0, O[ni][1] * inv0);
        *(__half2*)&cbase[(size_t)(g + 8) * DIM + c] =
            __floats2half2_rn(O[ni][2] * inv1, O[ni][3] * inv1);
    }
}

// ---------------- LayerNorm (fp32 in, fp32 + fp16 out) ----------------------
__global__ void ln_kernel(const float* __restrict__ x, const float* __restrict__ w,
                          const float* __restrict__ b, float* __restrict__ out32,
                          __half* __restrict__ out16) {
    int row = blockIdx.x;
    const float* xr = x + (size_t)row * DIM;
    float v[3];
    float s = 0.f, ss = 0.f;
#pragma unroll
    for (int i = 0; i < 3; i++) {
        v[i] = xr[threadIdx.x + i * 256];
        s += v[i]; ss += v[i] * v[i];
    }
    __shared__ float red0[8], red1[8];
    int lane = threadIdx.x & 31, wp = threadIdx.x >> 5;
#pragma unroll
    for (int o = 16; o; o >>= 1) {
        s  += __shfl_xor_sync(0xffffffffu, s, o);
        ss += __shfl_xor_sync(0xffffffffu, ss, o);
    }
    if (lane == 0) { red0[wp] = s; red1[wp] = ss; }
    __syncthreads();
    s = 0.f; ss = 0.f;
#pragma unroll
    for (int i = 0; i < 8; i++) { s += red0[i]; ss += red1[i]; }
    float mean = s * (1.f / DIM);
    float var  = ss * (1.f / DIM) - mean * mean;
    float inv  = rsqrtf(var + EPSI);
#pragma unroll
    for (int i = 0; i < 3; i++) {
        int c = threadIdx.x + i * 256;
        float y = (v[i] - mean) * inv * w[c] + b[c];
        if (out32) out32[(size_t)row * DIM + c] = y;
        out16[(size_t)row * DIM + c] = __float2half(y);
    }
}

// ---------------- per-head LN on fp16 qkv, in place --------------------------
__global__ void head_ln16_kernel(__half* __restrict__ qkv16, const float* __restrict__ w,
                                 const float* __restrict__ b, size_t nchunks) {
    size_t warp = ((size_t)blockIdx.x * blockDim.x + threadIdx.x) >> 5;
    int lane = threadIdx.x & 31;
    if (warp >= nchunks) return;
    __half2* ptr = (__half2*)(qkv16 + warp * 64);
    __half2 hv = ptr[lane];
    float x0 = __low2float(hv), x1 = __high2float(hv);
    float s = x0 + x1, ss = x0 * x0 + x1 * x1;
#pragma unroll
    for (int o = 16; o; o >>= 1) {
        s  += __shfl_xor_sync(0xffffffffu, s, o);
        ss += __shfl_xor_sync(0xffffffffu, ss, o);
    }
    float mean = s * (1.f / 64.f);
    float var  = ss * (1.f / 64.f) - mean * mean;
    float inv  = rsqrtf(var + EPSI);
    float y0 = (x0 - mean) * inv * w[2 * lane]     + b[2 * lane];
    float y1 = (x1 - mean) * inv * w[2 * lane + 1] + b[2 * lane + 1];
    ptr[lane] = __floats2half2_rn(y0, y1);
}

// ------- fused: res = xn + p[other] + remap(q16[other]); ln2(res) -----------
__global__ void res_ln2_kernel(const float* __restrict__ xn, const float* __restrict__ p,
                               const __half* __restrict__ qkv16,
                               const float* __restrict__ w, const float* __restrict__ b,
                               float* __restrict__ res, __half* __restrict__ ln216)
{
    int row = blockIdx.x;                       // dir*8192 + bb*1024 + n
    int dir = row >> 13, rem = row & 8191;
    int bb = rem >> 10, n = rem & 1023;
    int other = 1 - dir;
    const float* xr = xn + (size_t)row * DIM;
    const float* pr = p + ((size_t)other * 8192 + rem) * DIM;
    const __half* qbase = qkv16 + (size_t)(other * BATCH + bb) * SEQ * QKVC;

    float v[3];
    float s = 0.f, ss = 0.f;
#pragma unroll
    for (int i = 0; i < 3; i++) {
        int c = threadIdx.x + i * 256;
        int t = n * DIM + c;
        int h = t >> 16;
        int n2 = (t >> 6) & 1023;
        int d = t & 63;
        float qv = __half2float(qbase[(size_t)n2 * QKVC + h * HD + d]);
        v[i] = xr[c] + pr[c] + qv;
        s += v[i]; ss += v[i] * v[i];
    }
    __shared__ float red0[8], red1[8];
    int lane = threadIdx.x & 31, wp = threadIdx.x >> 5;
#pragma unroll
    for (int o = 16; o; o >>= 1) {
        s  += __shfl_xor_sync(0xffffffffu, s, o);
        ss += __shfl_xor_sync(0xffffffffu, ss, o);
    }
    if (lane == 0) { red0[wp] = s; red1[wp] = ss; }
    __syncthreads();
    s = 0.f; ss = 0.f;
#pragma unroll
    for (int i = 0; i < 8; i++) { s += red0[i]; ss += red1[i]; }
    float mean = s * (1.f / DIM);
    float var  = ss * (1.f / DIM) - mean * mean;
    float inv  = rsqrtf(var + EPSI);
#pragma unroll
    for (int i = 0; i < 3; i++) {
        int c = threadIdx.x + i * 256;
        res[(size_t)row * DIM + c] = v[i];
        float y = (v[i] - mean) * inv * w[c] + b[c];
        ln216[(size_t)row * DIM + c] = __float2half(y);
    }
}

// ---------------------------------------------------------------------------
extern "C" void kernel_launch(void* const* d_in, const int* in_sizes, int n_in,
                              void* d_out, int out_size) {
    const float* before  = (const float*)d_in[0];
    const float* after   = (const float*)d_in[1];
    const float* norm1_w = (const float*)d_in[2];
    const float* norm1_b = (const float*)d_in[3];
    const float* qkv_w   = (const float*)d_in[4];
    const float* hln_w   = (const float*)d_in[5];
    const float* hln_b   = (const float*)d_in[6];
    const float* proj_w  = (const float*)d_in[7];
    const float* proj_b  = (const float*)d_in[8];
    const float* norm2_w = (const float*)d_in[9];
    const float* norm2_b = (const float*)d_in[10];
    const float* fc1_w   = (const float*)d_in[11];
    const float* fc1_b   = (const float*)d_in[12];
    const float* fc2_w   = (const float*)d_in[13];
    const float* fc2_b   = (const float*)d_in[14];
    float* out = (float*)d_out;

    float  *xn, *p, *res;
    __half *xn16, *qkv16, *vt, *ctx16, *ln216, *h16, *w16;
    cudaGetSymbolAddress((void**)&xn,    g_xn);
    cudaGetSymbolAddress((void**)&p,     g_p);
    cudaGetSymbolAddress((void**)&res,   g_res);
    cudaGetSymbolAddress((void**)&xn16,  g_xn16);
    cudaGetSymbolAddress((void**)&qkv16, g_qkv16);
    cudaGetSymbolAddress((void**)&vt,    g_vt);
    cudaGetSymbolAddress((void**)&ctx16, g_ctx16);
    cudaGetSymbolAddress((void**)&ln216, g_ln216);
    cudaGetSymbolAddress((void**)&h16,   g_h16);
    cudaGetSymbolAddress((void**)&w16,   g_w16);

    const size_t BNC = (size_t)BATCH * SEQ * DIM;
    const int ROWS1 = BATCH * SEQ;          // 8192
    const int ROWS2 = 2 * ROWS1;            // 16384

    cudaFuncSetAttribute(hgemm<0,true ,false>, cudaFuncAttributeMaxDynamicSharedMemorySize, HS_BYTES);
    cudaFuncSetAttribute(hgemm<0,false,false>, cudaFuncAttributeMaxDynamicSharedMemorySize, HS_BYTES);
    cudaFuncSetAttribute(hgemm<1,true ,false>, cudaFuncAttributeMaxDynamicSharedMemorySize, HS_BYTES);
    cudaFuncSetAttribute(hgemm<0,false,true >, cudaFuncAttributeMaxDynamicSharedMemorySize, HS_BYTES);
    cudaFuncSetAttribute(flash_attn_kernel, cudaFuncAttributeMaxDynamicSharedMemorySize,
                         (int)sizeof(FlashSmemH));

    // 0. weight conversion (fp32 -> fp16)
    f2h_kernel<<<(QKVC * DIM / 4 + 255) / 256, 256>>>(qkv_w,  w16 + W16_QKV,  QKVC * DIM);
    f2h_kernel<<<(DIM * DIM / 4 + 255) / 256, 256>>>(proj_w, w16 + W16_PROJ, DIM * DIM);
    f2h_kernel<<<(HIDDEN * DIM / 4 + 255) / 256, 256>>>(fc1_w, w16 + W16_FC1, HIDDEN * DIM);
    f2h_kernel<<<(DIM * HIDDEN / 4 + 255) / 256, 256>>>(fc2_w, w16 + W16_FC2, DIM * HIDDEN);

    // 1. norm1 on both streams (fp32 + fp16 outputs)
    ln_kernel<<<ROWS1, 256>>>(before, norm1_w, norm1_b, xn,       xn16);
    ln_kernel<<<ROWS1, 256>>>(after,  norm1_w, norm1_b, xn + BNC, xn16 + BNC);

    // 2. fused-stream QKV GEMM -> fp16 qkv directly
    hgemm<0,true,false><<<dim3(QKVC/BN, ROWS2/BM), 256, HS_BYTES>>>(
        xn16, w16 + W16_QKV, nullptr, nullptr, qkv16, DIM, QKVC);

    // 3. per-head LN in place on fp16
    {
        size_t nchunks = (size_t)ROWS2 * QKVC / 64;
        int blocks = (int)((nchunks * 32 + 255) / 256);
        head_ln16_kernel<<<blocks, 256>>>(qkv16, hln_w, hln_b, nchunks);
    }

    // 3b. V transpose (fp16 -> fp16)
    vt_kernel<<<dim3(SEQ/64, 2*BATCH*NHEAD), 256>>>(qkv16, vt);

    // 4. fused fp16 flash cross-attention
    flash_attn_kernel<<<dim3(SEQ/QT, BATCH*NHEAD, 2), 256, sizeof(FlashSmemH)>>>(
        qkv16, vt, ctx16);

    // 5. output projection -> fp32 p
    hgemm<0,false,false><<<dim3(DIM/BN, ROWS2/BM), 256, HS_BYTES>>>(
        ctx16, w16 + W16_PROJ, proj_b, nullptr, p, DIM, DIM);

    // 6+7. fused attention residual (cross-stream swap + fp16 q-remap) + norm2
    res_ln2_kernel<<<ROWS2, 256>>>(xn, p, qkv16, norm2_w, norm2_b, res, ln216);

    // 8. MLP: fc1 + exact GELU -> fp16 h
    hgemm<1,true,false><<<dim3(HIDDEN/BN, ROWS2/BM), 256, HS_BYTES>>>(
        ln216, w16 + W16_FC1, fc1_b, nullptr, h16, DIM, HIDDEN);

    // 9. fc2 + bias + residual -> fp32 out
    hgemm<0,false,true><<<dim3(DIM/BN, ROWS2/BM), 256, HS_BYTES>>>(
        h16, w16 + W16_FC2, fc2_b, res, out, HIDDEN, DIM);
}

// round 14
// speedup vs baseline: 6.3299x; 1.0497x over previous
#include <cuda_runtime.h>
#include <cuda_fp16.h>
#include <math.h>
#include <stdint.h>

#define BATCH 8
#define SEQ 1024
#define DIM 768
#define NHEAD 12
#define HD 64
#define QKVC 2304
#define HIDDEN 3072
#define EPSI 1e-5f

// ---------------- scratch (device globals: allocation-free contract) --------
__device__ float  g_xn  [2ull*BATCH*SEQ*DIM];
__device__ float  g_p   [2ull*BATCH*SEQ*DIM];
__device__ float  g_res [2ull*BATCH*SEQ*DIM];
__device__ __half g_xn16 [2ull*BATCH*SEQ*DIM];
__device__ __half g_qkv16[2ull*BATCH*SEQ*QKVC];
__device__ __half g_vt   [2ull*BATCH*NHEAD*HD*SEQ];   // V transposed: [dir][b][h][d][kv]
__device__ __half g_ctx16[2ull*BATCH*SEQ*DIM];
__device__ __half g_ln216[2ull*BATCH*SEQ*DIM];
__device__ __half g_h16  [2ull*BATCH*SEQ*HIDDEN];
__device__ __half g_w16  [7077888];                   // qkv_w|proj_w|fc1_w|fc2_w

#define W16_QKV  0
#define W16_PROJ 1769472
#define W16_FC1  2359296
#define W16_FC2  4718592
#define W16_END  7077888

// ---------------- async copy helpers ---------------------------------------
__device__ __forceinline__ void cp_async16(uint32_t smem, const void* g) {
    asm volatile("cp.async.cg.shared.global [%0], [%1], 16;" :: "r"(smem), "l"(g));
}
__device__ __forceinline__ void cp_commit() {
    asm volatile("cp.async.commit_group;");
}
template<int N> __device__ __forceinline__ void cp_wait() {
    asm volatile("cp.async.wait_group %0;" :: "n"(N));
}
__device__ __forceinline__ uint32_t smem_u32(const void* p) {
    return (uint32_t)__cvta_generic_to_shared(p);
}
__device__ __forceinline__ uint32_t ld32h(const __half* p) {
    return *(const uint32_t*)p;
}
__device__ __forceinline__ void ldsm_x4(uint32_t* r, uint32_t addr) {
    asm volatile("ldmatrix.sync.aligned.m8n8.x4.shared.b16 {%0,%1,%2,%3}, [%4];"
        : "=r"(r[0]), "=r"(r[1]), "=r"(r[2]), "=r"(r[3]) : "r"(addr));
}

// ---------------- m16n8k16 fp16 mma (fp32 accum) ----------------------------
__device__ __forceinline__ void mma_f16(float* c, const uint32_t* a, const uint32_t* b) {
    asm volatile(
        "mma.sync.aligned.m16n8k16.row.col.f32.f16.f16.f32 "
        "{%0,%1,%2,%3}, {%4,%5,%6,%7}, {%8,%9}, {%0,%1,%2,%3};"
        : "+f"(c[0]), "+f"(c[1]), "+f"(c[2]), "+f"(c[3])
        : "r"(a[0]), "r"(a[1]), "r"(a[2]), "r"(a[3]), "r"(b[0]), "r"(b[1]));
}

// ---------------- merged fp32 -> fp16 weight convert ------------------------
__global__ void f2h_all_kernel(const float* __restrict__ a0, const float* __restrict__ a1,
                               const float* __restrict__ a2, const float* __restrict__ a3,
                               __half* __restrict__ y) {
    int i = (blockIdx.x * 256 + threadIdx.x) * 4;
    if (i >= W16_END) return;
    const float* src; int off;
    if (i < W16_PROJ)      { src = a0; off = i; }
    else if (i < W16_FC1)  { src = a1; off = i - W16_PROJ; }
    else if (i < W16_FC2)  { src = a2; off = i - W16_FC1; }
    else                   { src = a3; off = i - W16_FC2; }
    float4 v = *(const float4*)&src[off];
    *(__half2*)&y[i]     = __floats2half2_rn(v.x, v.y);
    *(__half2*)&y[i + 2] = __floats2half2_rn(v.z, v.w);
}

// ================= dense fp16 tensor-core GEMM (ldmatrix, 3-stage) ==========
// C = act(A @ W^T + bias) [+ resid].  A:(M,K) fp16, W:(N,K) fp16.
#define BM 128
#define BN 128
#define BK 32
#define SA 40          // smem row stride in halves (80 B, conflict-free)
#define NSTG 3
#define STG_A (BM * SA)
#define STG_B (BN * SA)
#define HS_BYTES (NSTG * (STG_A + STG_B) * 2)

template<int ACT, bool OUT_HALF, bool HAS_RES>
__global__ void __launch_bounds__(256)
hgemm(const __half* __restrict__ A, const __half* __restrict__ W,
      const float* __restrict__ bias, const float* __restrict__ resid,
      void* __restrict__ Cv, int K, int N)
{
    extern __shared__ __half sh[];
    __half* Asm = sh;
    __half* Bsm = sh + NSTG * STG_A;

    const int tid = threadIdx.x;
    const int lane = tid & 31, wid = tid >> 5;
    const int g = lane >> 2, t = lane & 3;
    const int wr = wid & 1, wc = wid >> 1;          // 2x4 warp grid: 64x32 tiles
    const int mB = wr * 64, nB = wc * 32;
    const int m0 = blockIdx.y * BM, n0 = blockIdx.x * BN;

    const int aRow = lane & 15;
    const int aCol = (lane >> 4) * 8;
    const int bRow = ((lane >> 4) << 3) + (lane & 7);
    const int bCol = ((lane >> 3) & 1) * 8;

    auto load_stage = [&](int s, int k0) {
        const __half* aSrc = A + (size_t)m0 * K + k0;
        __half* aDst = Asm + s * STG_A;
#pragma unroll
        for (int i = 0; i < 2; i++) {
            int l = tid + i * 256;
            int r = l >> 2, q = l & 3;
            cp_async16(smem_u32(&aDst[r * SA + q * 8]), aSrc + (size_t)r * K + q * 8);
        }
        const __half* bSrc = W + (size_t)n0 * K + k0;
        __half* bDst = Bsm + s * STG_B;
#pragma unroll
        for (int i = 0; i < 2; i++) {
            int l = tid + i * 256;
            int r = l >> 2, q = l & 3;
            cp_async16(smem_u32(&bDst[r * SA + q * 8]), bSrc + (size_t)r * K + q * 8);
        }
        cp_commit();
    };

    float acc[4][4][4];
#pragma unroll
    for (int mi = 0; mi < 4; mi++)
#pragma unroll
        for (int ni = 0; ni < 4; ni++)
#pragma unroll
            for (int r = 0; r < 4; r++) acc[mi][ni][r] = 0.f;

    const int T = K / BK;
    load_stage(0, 0);
    load_stage(1, BK);

    for (int it = 0; it < T; ++it) {
        const int cur = it % NSTG;
        // single barrier per iteration: all warps done with it-1 before the
        // prefetch below overwrites stage (it+2)%3 == (it-1)%3.
        if (it + 1 < T) {
            cp_wait<1>();
            __syncthreads();
            if (it + 2 < T) load_stage((it + 2) % NSTG, (it + 2) * BK);
        } else {
            cp_wait<0>();
            __syncthreads();
        }

        const __half* Ac = Asm + cur * STG_A;
        const __half* Bc = Bsm + cur * STG_B;
#pragma unroll
        for (int ks = 0; ks < 2; ks++) {
            uint32_t af[4][4];
#pragma unroll
            for (int mi = 0; mi < 4; mi++)
                ldsm_x4(af[mi], smem_u32(&Ac[(mB + mi * 16 + aRow) * SA + aCol + ks * 16]));
            uint32_t bf[4][2];
#pragma unroll
            for (int nip = 0; nip < 2; nip++) {
                uint32_t r4[4];
                ldsm_x4(r4, smem_u32(&Bc[(nB + nip * 16 + bRow) * SA + bCol + ks * 16]));
                bf[2 * nip    ][0] = r4[0]; bf[2 * nip    ][1] = r4[1];
                bf[2 * nip + 1][0] = r4[2]; bf[2 * nip + 1][1] = r4[3];
            }
#pragma unroll
            for (int mi = 0; mi < 4; mi++)
#pragma unroll
                for (int ni = 0; ni < 4; ni++)
                    mma_f16(acc[mi][ni], af[mi], bf[ni]);
        }
    }

    // epilogue
#pragma unroll
    for (int mi = 0; mi < 4; mi++) {
        int r0 = m0 + mB + mi * 16 + g;
        int r1 = r0 + 8;
#pragma unroll
        for (int ni = 0; ni < 4; ni++) {
            int c = n0 + nB + ni * 8 + 2 * t;
            float v[4] = { acc[mi][ni][0], acc[mi][ni][1], acc[mi][ni][2], acc[mi][ni][3] };
            if (bias) {
                float b0 = bias[c], b1 = bias[c + 1];
                v[0] += b0; v[1] += b1; v[2] += b0; v[3] += b1;
            }
            if (ACT == 1) {
#pragma unroll
                for (int r = 0; r < 4; r++)
                    v[r] = 0.5f * v[r] * (1.f + erff(v[r] * 0.70710678118654752f));
            }
            if (HAS_RES) {
                v[0] += resid[(size_t)r0 * N + c];
                v[1] += resid[(size_t)r0 * N + c + 1];
                v[2] += resid[(size_t)r1 * N + c];
                v[3] += resid[(size_t)r1 * N + c + 1];
            }
            if (OUT_HALF) {
                __half* Ch = (__half*)Cv;
                *(__half2*)&Ch[(size_t)r0 * N + c] = __floats2half2_rn(v[0], v[1]);
                *(__half2*)&Ch[(size_t)r1 * N + c] = __floats2half2_rn(v[2], v[3]);
            } else {
                float* Cf = (float*)Cv;
                *(float2*)&Cf[(size_t)r0 * N + c] = make_float2(v[0], v[1]);
                *(float2*)&Cf[(size_t)r1 * N + c] = make_float2(v[2], v[3]);
            }
        }
    }
}

// ================= V transpose: qkv16 -> Vt fp16 [dbh][d][kv] ===============
__global__ void vt_kernel(const __half* __restrict__ qkv16, __half* __restrict__ vt)
{
    __shared__ __half s[64][72];
    const int dbh = blockIdx.y;
    const int kv0 = blockIdx.x * 64;
    const int dir = dbh / 96, rem = dbh % 96;
    const int b = rem / NHEAD, h = rem % NHEAD;
    const int tid = threadIdx.x;
    const __half* src = qkv16 + ((size_t)(dir * BATCH + b) * SEQ) * QKVC + 2 * DIM + h * HD;
    for (int l = tid; l < 64 * 64; l += 256) {
        int r = l >> 6, c = l & 63;
        s[c][r] = src[(size_t)(kv0 + r) * QKVC + c];
    }
    __syncthreads();
    __half* dst = vt + (size_t)dbh * HD * SEQ + kv0;
    for (int l = tid; l < 64 * 64; l += 256) {
        int d = l >> 6, kk = l & 63;
        dst[(size_t)d * SEQ + kk] = s[d][kk];
    }
}

// ================= fused fp16 flash cross-attention =========================
#define QT 128
#define KT 64

struct FlashSmemH {
    __half Q[QT][72];
    __half K[2][KT][72];
    __half Vt[2][HD][72];
    __half P[QT][72];
};

__global__ void __launch_bounds__(256)
flash_attn_kernel(const __half* __restrict__ qkv16, const __half* __restrict__ vt,
                  __half* __restrict__ ctx16)
{
    extern __shared__ char smraw[];
    FlashSmemH& sm = *reinterpret_cast<FlashSmemH*>(smraw);
    const int tid  = threadIdx.x;
    const int lane = tid & 31, w = tid >> 5;
    const int g = lane >> 2, t = lane & 3;
    const int mB = w * 16;

    const int q0  = blockIdx.x * QT;
    const int bh  = blockIdx.y;
    const int b   = bh / NHEAD, h = bh - b * NHEAD;
    const int dir = blockIdx.z;

    const __half* qb = qkv16 + ((size_t)(dir * BATCH + b) * SEQ) * QKVC + h * HD;
    const __half* kb = qkv16 + ((size_t)((1 - dir) * BATCH + b) * SEQ) * QKVC + DIM + h * HD;
    const __half* vtb = vt + (size_t)((1 - dir) * 96 + b * NHEAD + h) * HD * SEQ;

    for (int l = tid; l < QT * 8; l += 256) {
        int r = l >> 3, c = (l & 7) * 8;
        cp_async16(smem_u32(&sm.Q[r][c]), qb + (size_t)(q0 + r) * QKVC + c);
    }
    for (int l = tid; l < KT * 8; l += 256) {
        int r = l >> 3, c = (l & 7) * 8;
        cp_async16(smem_u32(&sm.K[0][r][c]),  kb  + (size_t)r * QKVC + c);
        cp_async16(smem_u32(&sm.Vt[0][r][c]), vtb + (size_t)r * SEQ + c);
    }
    cp_commit();

    float m0 = -1e30f, m1 = -1e30f, l0 = 0.f, l1 = 0.f;
    float O[8][4] = {};

    const int NIT = SEQ / KT;
    for (int it = 0; it < NIT; ++it) {
        if (it + 1 < NIT) {
            const int nb = (it + 1) & 1;
            const int kv = (it + 1) * KT;
            for (int l = tid; l < KT * 8; l += 256) {
                int r = l >> 3, c = (l & 7) * 8;
                cp_async16(smem_u32(&sm.K[nb][r][c]),  kb  + (size_t)(kv + r) * QKVC + c);
                cp_async16(smem_u32(&sm.Vt[nb][r][c]), vtb + (size_t)r * SEQ + kv + c);
            }
            cp_commit();
            cp_wait<1>();
        } else {
            cp_wait<0>();
        }
        __syncthreads();
        const int buf = it & 1;

        float sf[8][4] = {};
#pragma unroll
        for (int ks = 0; ks < 4; ks++) {
            int kc = ks * 16 + 2 * t;
            uint32_t af[4];
            af[0] = ld32h(&sm.Q[mB + g    ][kc    ]);
            af[1] = ld32h(&sm.Q[mB + g + 8][kc    ]);
            af[2] = ld32h(&sm.Q[mB + g    ][kc + 8]);
            af[3] = ld32h(&sm.Q[mB + g + 8][kc + 8]);
#pragma unroll
            for (int ni = 0; ni < 8; ni++) {
                uint32_t bf[2] = { ld32h(&sm.K[buf][ni * 8 + g][kc    ]),
                                   ld32h(&sm.K[buf][ni * 8 + g][kc + 8]) };
                mma_f16(sf[ni], af, bf);
            }
        }

        float mx0 = -1e30f, mx1 = -1e30f;
#pragma unroll
        for (int ni = 0; ni < 8; ni++) {
#pragma unroll
            for (int c = 0; c < 4; c++) sf[ni][c] *= 0.125f;
            mx0 = fmaxf(mx0, fmaxf(sf[ni][0], sf[ni][1]));
            mx1 = fmaxf(mx1, fmaxf(sf[ni][2], sf[ni][3]));
        }
        mx0 = fmaxf(mx0, __shfl_xor_sync(0xffffffffu, mx0, 1));
        mx0 = fmaxf(mx0, __shfl_xor_sync(0xffffffffu, mx0, 2));
        mx1 = fmaxf(mx1, __shfl_xor_sync(0xffffffffu, mx1, 1));
        mx1 = fmaxf(mx1, __shfl_xor_sync(0xffffffffu, mx1, 2));
        const float nm0 = fmaxf(m0, mx0), nm1 = fmaxf(m1, mx1);
        const float a0 = __expf(m0 - nm0), a1 = __expf(m1 - nm1);
        m0 = nm0; m1 = nm1;

        float s0 = 0.f, s1 = 0.f;
#pragma unroll
        for (int ni = 0; ni < 8; ni++) {
            sf[ni][0] = __expf(sf[ni][0] - m0);
            sf[ni][1] = __expf(sf[ni][1] - m0);
            sf[ni][2] = __expf(sf[ni][2] - m1);
            sf[ni][3] = __expf(sf[ni][3] - m1);
            s0 += sf[ni][0] + sf[ni][1];
            s1 += sf[ni][2] + sf[ni][3];
            *(__half2*)&sm.P[mB + g    ][ni * 8 + 2 * t] = __floats2half2_rn(sf[ni][0], sf[ni][1]);
            *(__half2*)&sm.P[mB + g + 8][ni * 8 + 2 * t] = __floats2half2_rn(sf[ni][2], sf[ni][3]);
        }
        s0 += __shfl_xor_sync(0xffffffffu, s0, 1);
        s0 += __shfl_xor_sync(0xffffffffu, s0, 2);
        s1 += __shfl_xor_sync(0xffffffffu, s1, 1);
        s1 += __shfl_xor_sync(0xffffffffu, s1, 2);
        l0 = l0 * a0 + s0;
        l1 = l1 * a1 + s1;
#pragma unroll
        for (int ni = 0; ni < 8; ni++) {
            O[ni][0] *= a0; O[ni][1] *= a0;
            O[ni][2] *= a1; O[ni][3] *= a1;
        }
        __syncwarp();

#pragma unroll
        for (int ks = 0; ks < 4; ks++) {
            int kc = ks * 16 + 2 * t;
            uint32_t af[4];
            af[0] = ld32h(&sm.P[mB + g    ][kc    ]);
            af[1] = ld32h(&sm.P[mB + g + 8][kc    ]);
            af[2] = ld32h(&sm.P[mB + g    ][kc + 8]);
            af[3] = ld32h(&sm.P[mB + g + 8][kc + 8]);
#pragma unroll
            for (int ni = 0; ni < 8; ni++) {
                uint32_t bf[2] = { ld32h(&sm.Vt[buf][ni * 8 + g][kc    ]),
                                   ld32h(&sm.Vt[buf][ni * 8 + g][kc + 8]) };
                mma_f16(O[ni], af, bf);
            }
        }
        __syncthreads();
    }

    const float inv0 = 1.f / l0, inv1 = 1.f / l1;
    __half* cbase = ctx16 + ((size_t)(dir * BATCH + b) * SEQ + q0 + mB) * DIM + h * HD;
#pragma unroll
    for (int ni = 0; ni < 8; ni++) {
        int c = ni * 8 + 2 * t;
        *(__half2*)&cbase[(size_t)(g    ) * DIM + c] =
            __floats2half2_rn(O[ni][0] * inv0, O[ni][1] * inv0);
        *(__half2*)&cbase[(size_t)(g + 8) * DIM + c] =
            __floats2half2_rn(O[ni][2] * inv1, O[ni][3] * inv1);
    }
}

// ---------------- norm1 (both streams in one launch), vectorized ------------
// grid = 2*ROWS1, block = 192. row<8192: before, else after.
__global__ void __launch_bounds__(192)
ln1_kernel(const float* __restrict__ before, const float* __restrict__ after,
           const float* __restrict__ w, const float* __restrict__ b,
           float* __restrict__ out32, __half* __restrict__ out16) {
    int row = blockIdx.x;
    const float* x = (row < BATCH * SEQ) ? before : after;
    const float* xr = x + (size_t)(row & 8191) * DIM;
    int c = threadIdx.x * 4;
    float4 v = *(const float4*)&xr[c];
    float s = v.x + v.y + v.z + v.w;
    float ss = v.x * v.x + v.y * v.y + v.z * v.z + v.w * v.w;
    __shared__ float red0[6], red1[6];
    int lane = threadIdx.x & 31, wp = threadIdx.x >> 5;
#pragma unroll
    for (int o = 16; o; o >>= 1) {
        s  += __shfl_xor_sync(0xffffffffu, s, o);
        ss += __shfl_xor_sync(0xffffffffu, ss, o);
    }
    if (lane == 0) { red0[wp] = s; red1[wp] = ss; }
    __syncthreads();
    s = 0.f; ss = 0.f;
#pragma unroll
    for (int i = 0; i < 6; i++) { s += red0[i]; ss += red1[i]; }
    float mean = s * (1.f / DIM);
    float var  = ss * (1.f / DIM) - mean * mean;
    float inv  = rsqrtf(var + EPSI);
    float4 wv = *(const float4*)&w[c];
    float4 bv = *(const float4*)&b[c];
    float y0 = (v.x - mean) * inv * wv.x + bv.x;
    float y1 = (v.y - mean) * inv * wv.y + bv.y;
    float y2 = (v.z - mean) * inv * wv.z + bv.z;
    float y3 = (v.w - mean) * inv * wv.w + bv.w;
    *(float4*)&out32[(size_t)row * DIM + c] = make_float4(y0, y1, y2, y3);
    __half2 h01 = __floats2half2_rn(y0, y1), h23 = __floats2half2_rn(y2, y3);
    *(__half2*)&out16[(size_t)row * DIM + c]     = h01;
    *(__half2*)&out16[(size_t)row * DIM + c + 2] = h23;
}

// ---------------- per-head LN on fp16 qkv, 2 chunks per warp ----------------
__global__ void head_ln16_kernel(__half* __restrict__ qkv16, const float* __restrict__ w,
                                 const float* __restrict__ b, size_t npairs) {
    size_t warp = ((size_t)blockIdx.x * blockDim.x + threadIdx.x) >> 5;
    int lane = threadIdx.x & 31;
    if (warp >= npairs) return;
    // warp handles 2 chunks of 64; lanes 0-15 chunk A, 16-31 chunk B
    uint2* base = (uint2*)(qkv16 + warp * 128);
    uint2 raw = base[lane];                 // 4 halves at position (lane&15)*4 of its chunk
    __half2 h01 = *(__half2*)&raw.x, h23 = *(__half2*)&raw.y;
    float x0 = __low2float(h01), x1 = __high2float(h01);
    float x2 = __low2float(h23), x3 = __high2float(h23);
    float s = x0 + x1 + x2 + x3;
    float ss = x0 * x0 + x1 * x1 + x2 * x2 + x3 * x3;
#pragma unroll
    for (int o = 8; o; o >>= 1) {           // reduce within 16-lane group
        s  += __shfl_xor_sync(0xffffffffu, s, o);
        ss += __shfl_xor_sync(0xffffffffu, ss, o);
    }
    float mean = s * (1.f / 64.f);
    float var  = ss * (1.f / 64.f) - mean * mean;
    float inv  = rsqrtf(var + EPSI);
    int pos = (lane & 15) * 4;
    float4 wv = *(const float4*)&w[pos];
    float4 bv = *(const float4*)&b[pos];
    float y0 = (x0 - mean) * inv * wv.x + bv.x;
    float y1 = (x1 - mean) * inv * wv.y + bv.y;
    float y2 = (x2 - mean) * inv * wv.z + bv.z;
    float y3 = (x3 - mean) * inv * wv.w + bv.w;
    uint2 out;
    *(__half2*)&out.x = __floats2half2_rn(y0, y1);
    *(__half2*)&out.y = __floats2half2_rn(y2, y3);
    base[lane] = out;
}

// ------- fused: res = xn + p[other] + remap(q16[other]); ln2(res) -----------
__global__ void __launch_bounds__(192)
res_ln2_kernel(const float* __restrict__ xn, const float* __restrict__ p,
               const __half* __restrict__ qkv16,
               const float* __restrict__ w, const float* __restrict__ b,
               float* __restrict__ res, __half* __restrict__ ln216)
{
    int row = blockIdx.x;                       // dir*8192 + bb*1024 + n
    int dir = row >> 13, rem = row & 8191;
    int bb = (rem >> 10) & 7, n = rem & 1023;
    int other = 1 - dir;
    const float* xr = xn + (size_t)row * DIM;
    const float* pr = p + ((size_t)other * 8192 + rem) * DIM;
    const __half* qbase = qkv16 + (size_t)(other * BATCH + bb) * SEQ * QKVC;

    int c = threadIdx.x * 4;
    int tq = n * DIM + c;
    int h = tq >> 16;
    int n2 = (tq >> 6) & 1023;
    int d = tq & 63;                            // d..d+3 within one 64-chunk (c%4==0)
    uint2 qraw = *(const uint2*)&qbase[(size_t)n2 * QKVC + h * HD + d];
    __half2 q01 = *(__half2*)&qraw.x, q23 = *(__half2*)&qraw.y;

    float4 xv = *(const float4*)&xr[c];
    float4 pv = *(const float4*)&pr[c];
    float v0 = xv.x + pv.x + __low2float(q01);
    float v1 = xv.y + pv.y + __high2float(q01);
    float v2 = xv.z + pv.z + __low2float(q23);
    float v3 = xv.w + pv.w + __high2float(q23);

    float s = v0 + v1 + v2 + v3;
    float ss = v0 * v0 + v1 * v1 + v2 * v2 + v3 * v3;
    __shared__ float red0[6], red1[6];
    int lane = threadIdx.x & 31, wp = threadIdx.x >> 5;
#pragma unroll
    for (int o = 16; o; o >>= 1) {
        s  += __shfl_xor_sync(0xffffffffu, s, o);
        ss += __shfl_xor_sync(0xffffffffu, ss, o);
    }
    if (lane == 0) { red0[wp] = s; red1[wp] = ss; }
    __syncthreads();
    s = 0.f; ss = 0.f;
#pragma unroll
    for (int i = 0; i < 6; i++) { s += red0[i]; ss += red1[i]; }
    float mean = s * (1.f / DIM);
    float var  = ss * (1.f / DIM) - mean * mean;
    float inv  = rsqrtf(var + EPSI);

    *(float4*)&res[(size_t)row * DIM + c] = make_float4(v0, v1, v2, v3);
    float4 wv = *(const float4*)&w[c];
    float4 bv = *(const float4*)&b[c];
    float y0 = (v0 - mean) * inv * wv.x + bv.x;
    float y1 = (v1 - mean) * inv * wv.y + bv.y;
    float y2 = (v2 - mean) * inv * wv.z + bv.z;
    float y3 = (v3 - mean) * inv * wv.w + bv.w;
    *(__half2*)&ln216[(size_t)row * DIM + c]     = __floats2half2_rn(y0, y1);
    *(__half2*)&ln216[(size_t)row * DIM + c + 2] = __floats2half2_rn(y2, y3);
}

// ---------------------------------------------------------------------------
extern "C" void kernel_launch(void* const* d_in, const int* in_sizes, int n_in,
                              void* d_out, int out_size) {
    const float* before  = (const float*)d_in[0];
    const float* after   = (const float*)d_in[1];
    const float* norm1_w = (const float*)d_in[2];
    const float* norm1_b = (const float*)d_in[3];
    const float* qkv_w   = (const float*)d_in[4];
    const float* hln_w   = (const float*)d_in[5];
    const float* hln_b   = (const float*)d_in[6];
    const float* proj_w  = (const float*)d_in[7];
    const float* proj_b  = (const float*)d_in[8];
    const float* norm2_w = (const float*)d_in[9];
    const float* norm2_b = (const float*)d_in[10];
    const float* fc1_w   = (const float*)d_in[11];
    const float* fc1_b   = (const float*)d_in[12];
    const float* fc2_w   = (const float*)d_in[13];
    const float* fc2_b   = (const float*)d_in[14];
    float* out = (float*)d_out;

    float  *xn, *p, *res;
    __half *xn16, *qkv16, *vt, *ctx16, *ln216, *h16, *w16;
    cudaGetSymbolAddress((void**)&xn,    g_xn);
    cudaGetSymbolAddress((void**)&p,     g_p);
    cudaGetSymbolAddress((void**)&res,   g_res);
    cudaGetSymbolAddress((void**)&xn16,  g_xn16);
    cudaGetSymbolAddress((void**)&qkv16, g_qkv16);
    cudaGetSymbolAddress((void**)&vt,    g_vt);
    cudaGetSymbolAddress((void**)&ctx16, g_ctx16);
    cudaGetSymbolAddress((void**)&ln216, g_ln216);
    cudaGetSymbolAddress((void**)&h16,   g_h16);
    cudaGetSymbolAddress((void**)&w16,   g_w16);

    const int ROWS2 = 2 * BATCH * SEQ;      // 16384

    cudaFuncSetAttribute(hgemm<0,true ,false>, cudaFuncAttributeMaxDynamicSharedMemorySize, HS_BYTES);
    cudaFuncSetAttribute(hgemm<0,false,false>, cudaFuncAttributeMaxDynamicSharedMemorySize, HS_BYTES);
    cudaFuncSetAttribute(hgemm<1,true ,false>, cudaFuncAttributeMaxDynamicSharedMemorySize, HS_BYTES);
    cudaFuncSetAttribute(hgemm<0,false,true >, cudaFuncAttributeMaxDynamicSharedMemorySize, HS_BYTES);
    cudaFuncSetAttribute(flash_attn_kernel, cudaFuncAttributeMaxDynamicSharedMemorySize,
                         (int)sizeof(FlashSmemH));

    // 0. merged weight conversion (fp32 -> fp16)
    f2h_all_kernel<<<(W16_END / 4 + 255) / 256, 256>>>(qkv_w, proj_w, fc1_w, fc2_w, w16);

    // 1. norm1, both streams in one launch
    ln1_kernel<<<ROWS2, 192>>>(before, after, norm1_w, norm1_b, xn, xn16);

    // 2. fused-stream QKV GEMM -> fp16 qkv directly
    hgemm<0,true,false><<<dim3(QKVC/BN, ROWS2/BM), 256, HS_BYTES>>>(
        xn16, w16 + W16_QKV, nullptr, nullptr, qkv16, DIM, QKVC);

    // 3. per-head LN in place on fp16 (2 chunks/warp)
    {
        size_t npairs = (size_t)ROWS2 * QKVC / 128;   // 294912
        int blocks = (int)((npairs * 32 + 255) / 256);
        head_ln16_kernel<<<blocks, 256>>>(qkv16, hln_w, hln_b, npairs);
    }

    // 3b. V transpose (fp16 -> fp16)
    vt_kernel<<<dim3(SEQ/64, 2*BATCH*NHEAD), 256>>>(qkv16, vt);

    // 4. fused fp16 flash cross-attention
    flash_attn_kernel<<<dim3(SEQ/QT, BATCH*NHEAD, 2), 256, sizeof(FlashSmemH)>>>(
        qkv16, vt, ctx16);

    // 5. output projection -> fp32 p
    hgemm<0,false,false><<<dim3(DIM/BN, ROWS2/BM), 256, HS_BYTES>>>(
        ctx16, w16 + W16_PROJ, proj_b, nullptr, p, DIM, DIM);

    // 6+7. fused attention residual (cross-stream swap + fp16 q-remap) + norm2
    res_ln2_kernel<<<ROWS2, 192>>>(xn, p, qkv16, norm2_w, norm2_b, res, ln216);

    // 8. MLP: fc1 + exact GELU -> fp16 h
    hgemm<1,true,false><<<dim3(HIDDEN/BN, ROWS2/BM), 256, HS_BYTES>>>(
        ln216, w16 + W16_FC1, fc1_b, nullptr, h16, DIM, HIDDEN);

    // 9. fc2 + bias + residual -> fp32 out
    hgemm<0,false,true><<<dim3(DIM/BN, ROWS2/BM), 256, HS_BYTES>>>(
        h16, w16 + W16_FC2, fc2_b, res, out, HIDDEN, DIM);
}